// round 1
// baseline (speedup 1.0000x reference)
#include <cuda_runtime.h>
#include <cstddef>

#define VOCAB   50000
#define XS      300
#define HS      150
#define HS3     450
#define NC      5
#define DEPTH   18
#define NNODES  524287      // 2^19 - 1
#define LEAVES  262144      // 2^18

// ---------------- scratch (static device globals; no allocation) ----------------
__device__ float g_EWi[(size_t)VOCAB * HS3];          // emb @ W_iou   (50000 x 450)
__device__ float g_EWf[(size_t)VOCAB * HS];           // emb @ W_f     (50000 x 150)
__device__ float g_h[(size_t)NNODES * HS];            // hidden state per node
__device__ float g_c[(size_t)NNODES * HS];            // cell state per node
__device__ float g_hsum[(size_t)(LEAVES / 2) * HS];   // h_l + h_r per parent (max 131072 rows)
__device__ float g_hiou[(size_t)(LEAVES / 2) * HS3];  // hsum @ U_iou
__device__ float g_hUf[(size_t)LEAVES * HS];          // child h @ U_f

// ---------------- FMA-only activations (args provably small; exact fallback) ----
__device__ __forceinline__ float sig_f(float x) {
    float ax = fabsf(x);
    if (ax > 1.0f) {                        // statistically never taken (>= ~16 sigma)
        return 1.0f / (1.0f + __expf(-x));
    }
    // sigmoid(x) = 0.5 + x*(1/4 - x^2/48 + x^4/480 - 17 x^6/80640 + 31 x^8/1451520)
    float x2 = x * x;
    float p = fmaf(x2, 2.1357958e-5f, -2.1081349e-4f);
    p = fmaf(x2, p, 2.0833333e-3f);
    p = fmaf(x2, p, -2.0833333e-2f);
    p = fmaf(x2, p, 0.25f);
    return fmaf(x, p, 0.5f);
}

__device__ __forceinline__ float tanh_f(float x) {
    float ax = fabsf(x);
    if (ax > 0.55f) {                       // statistically never taken
        float t = __expf(-2.0f * ax);
        float r = __fdividef(1.0f - t, 1.0f + t);
        return x < 0.0f ? -r : r;
    }
    // tanh(x) = x*(1 - x^2/3 + 2 x^4/15 - 17 x^6/315 + 62 x^8/2835)
    float x2 = x * x;
    float p = fmaf(x2, 2.1869488e-2f, -5.3968254e-2f);
    p = fmaf(x2, p, 1.3333333e-1f);
    p = fmaf(x2, p, -3.3333333e-1f);
    p = fmaf(x2, p, 1.0f);
    return x * p;
}

// ---------------- generic guarded fp32 tiled GEMM: C[M,N] = A[M,K] @ B[K,N] -----
// Row-major, lda == K, ldb == N, ldc == N.
__global__ __launch_bounds__(256) void k_sgemm(
    const float* __restrict__ A, const float* __restrict__ B, float* __restrict__ C,
    int M, int N, int K)
{
    __shared__ float As[16][65];   // As[k][m] (transposed, +1 pad)
    __shared__ float Bs[16][64];   // Bs[k][n]

    const int row0 = blockIdx.y * 64;
    const int col0 = blockIdx.x * 64;
    const int tx = threadIdx.x & 15;        // 16 col groups
    const int ty = threadIdx.x >> 4;        // 16 row groups

    float acc[4][4] = {};

    for (int k0 = 0; k0 < K; k0 += 16) {
        // load A tile 64x16 (coalesced along k)
        for (int i = threadIdx.x; i < 64 * 16; i += 256) {
            int r = i >> 4, c = i & 15;
            int gr = row0 + r, gc = k0 + c;
            As[c][r] = (gr < M && gc < K) ? A[(size_t)gr * K + gc] : 0.0f;
        }
        // load B tile 16x64 (coalesced along n)
        for (int i = threadIdx.x; i < 16 * 64; i += 256) {
            int r = i >> 6, c = i & 63;
            int gr = k0 + r, gc = col0 + c;
            Bs[r][c] = (gr < K && gc < N) ? B[(size_t)gr * N + gc] : 0.0f;
        }
        __syncthreads();
        #pragma unroll
        for (int kk = 0; kk < 16; kk++) {
            float a[4], b[4];
            #pragma unroll
            for (int m = 0; m < 4; m++) a[m] = As[kk][ty * 4 + m];
            #pragma unroll
            for (int n = 0; n < 4; n++) b[n] = Bs[kk][tx * 4 + n];
            #pragma unroll
            for (int m = 0; m < 4; m++)
                #pragma unroll
                for (int n = 0; n < 4; n++)
                    acc[m][n] = fmaf(a[m], b[n], acc[m][n]);
        }
        __syncthreads();
    }

    #pragma unroll
    for (int m = 0; m < 4; m++) {
        int gr = row0 + ty * 4 + m;
        if (gr >= M) continue;
        #pragma unroll
        for (int n = 0; n < 4; n++) {
            int gc = col0 + tx * 4 + n;
            if (gc < N) C[(size_t)gr * N + gc] = acc[m][n];
        }
    }
}

// ---------------- leaf level: iou = EWi[xid] + b_iou; no children -----------------
__global__ void k_leaf(const int* __restrict__ xid, const float* __restrict__ biou)
{
    int idx = blockIdx.x * blockDim.x + threadIdx.x;
    const int total = LEAVES * HS;
    if (idx >= total) return;
    int i = idx / HS;
    int j = idx - i * HS;
    int n = (LEAVES - 1) + i;
    const float* ew = g_EWi + (size_t)xid[n] * HS3;
    float iv = ew[j] + biou[j];
    float ov = ew[HS + j] + biou[HS + j];
    float uv = ew[2 * HS + j] + biou[2 * HS + j];
    float cv = sig_f(iv) * tanh_f(uv);
    float hv = sig_f(ov) * tanh_f(cv);
    size_t o = (size_t)n * HS + j;
    g_c[o] = cv;
    g_h[o] = hv;
}

// ---------------- pair sum of children h for the U_iou GEMM ----------------------
__global__ void k_pairsum(int cs, int M)
{
    int idx = blockIdx.x * blockDim.x + threadIdx.x;
    const int total = M * HS;
    if (idx >= total) return;
    int k = idx / HS;
    int j = idx - k * HS;
    g_hsum[idx] = g_h[(size_t)(cs + 2 * k) * HS + j] + g_h[(size_t)(cs + 2 * k + 1) * HS + j];
}

// ---------------- gate combine for one internal level ----------------------------
__global__ void k_combine(int s, int cs, int M, const int* __restrict__ xid,
                          const float* __restrict__ biou, const float* __restrict__ bf)
{
    int idx = blockIdx.x * blockDim.x + threadIdx.x;
    const int total = M * HS;
    if (idx >= total) return;
    int k = idx / HS;
    int j = idx - k * HS;
    int p = s + k;
    int v = xid[p];
    const float* ewi = g_EWi + (size_t)v * HS3;
    const float* ewf = g_EWf + (size_t)v * HS;
    const float* hio = g_hiou + (size_t)k * HS3;

    float iv = ewi[j]          + hio[j]          + biou[j];
    float ov = ewi[HS + j]     + hio[HS + j]     + biou[HS + j];
    float uv = ewi[2 * HS + j] + hio[2 * HS + j] + biou[2 * HS + j];
    float xf = ewf[j] + bf[j];
    float fl = sig_f(xf + g_hUf[(size_t)(2 * k) * HS + j]);
    float fr = sig_f(xf + g_hUf[(size_t)(2 * k + 1) * HS + j]);
    float cl = g_c[(size_t)(cs + 2 * k) * HS + j];
    float cr = g_c[(size_t)(cs + 2 * k + 1) * HS + j];

    float cv = sig_f(iv) * tanh_f(uv) + fl * cl + fr * cr;
    float hv = sig_f(ov) * tanh_f(cv);
    size_t o = (size_t)p * HS + j;
    g_c[o] = cv;
    g_h[o] = hv;
}

// ---------------- output projection: out = h @ W_out + b_out  (warp per node) ----
__global__ void k_out(const float* __restrict__ Wout, const float* __restrict__ bout,
                      float* __restrict__ out)
{
    __shared__ float sW[HS * NC];
    for (int i = threadIdx.x; i < HS * NC; i += blockDim.x) sW[i] = Wout[i];
    __syncthreads();

    int gw = (blockIdx.x * blockDim.x + threadIdx.x) >> 5;
    int lane = threadIdx.x & 31;
    if (gw >= NNODES) return;

    const float* h = g_h + (size_t)gw * HS;
    float a0 = 0.f, a1 = 0.f, a2 = 0.f, a3 = 0.f, a4 = 0.f;
    for (int j = lane; j < HS; j += 32) {
        float hv = h[j];
        const float* w = sW + j * NC;
        a0 = fmaf(hv, w[0], a0);
        a1 = fmaf(hv, w[1], a1);
        a2 = fmaf(hv, w[2], a2);
        a3 = fmaf(hv, w[3], a3);
        a4 = fmaf(hv, w[4], a4);
    }
    #pragma unroll
    for (int off = 16; off; off >>= 1) {
        a0 += __shfl_xor_sync(0xffffffffu, a0, off);
        a1 += __shfl_xor_sync(0xffffffffu, a1, off);
        a2 += __shfl_xor_sync(0xffffffffu, a2, off);
        a3 += __shfl_xor_sync(0xffffffffu, a3, off);
        a4 += __shfl_xor_sync(0xffffffffu, a4, off);
    }
    if (lane == 0) {
        float* o = out + (size_t)gw * NC;
        o[0] = a0 + bout[0];
        o[1] = a1 + bout[1];
        o[2] = a2 + bout[2];
        o[3] = a3 + bout[3];
        o[4] = a4 + bout[4];
    }
}

// ---------------- host orchestration (graph-capturable: launches only) -----------
static inline dim3 gemm_grid(int M, int N) {
    return dim3((unsigned)((N + 63) / 64), (unsigned)((M + 63) / 64));
}

extern "C" void kernel_launch(void* const* d_in, const int* in_sizes, int n_in,
                              void* d_out, int out_size)
{
    (void)in_sizes; (void)n_in; (void)out_size;
    const int*   xid  = (const int*)d_in[0];
    const float* emb  = (const float*)d_in[1];
    const float* Wiou = (const float*)d_in[2];
    const float* Uiou = (const float*)d_in[3];
    const float* biou = (const float*)d_in[4];
    const float* Wf   = (const float*)d_in[5];
    const float* Uf   = (const float*)d_in[6];
    const float* bf   = (const float*)d_in[7];
    const float* Wout = (const float*)d_in[8];
    const float* bout = (const float*)d_in[9];
    float* out = (float*)d_out;

    float *pEWi, *pEWf, *ph, *phsum, *phiou, *phUf;
    cudaGetSymbolAddress((void**)&pEWi,  g_EWi);
    cudaGetSymbolAddress((void**)&pEWf,  g_EWf);
    cudaGetSymbolAddress((void**)&ph,    g_h);
    cudaGetSymbolAddress((void**)&phsum, g_hsum);
    cudaGetSymbolAddress((void**)&phiou, g_hiou);
    cudaGetSymbolAddress((void**)&phUf,  g_hUf);

    const dim3 thr(256);

    // Precompute per-vocab input projections: 18 GFLOP instead of 189.
    k_sgemm<<<gemm_grid(VOCAB, HS3), thr>>>(emb, Wiou, pEWi, VOCAB, HS3, XS);
    k_sgemm<<<gemm_grid(VOCAB, HS),  thr>>>(emb, Wf,   pEWf, VOCAB, HS,  XS);

    // Leaf level (262144 nodes): pure gather + gates.
    k_leaf<<<(LEAVES * HS + 255) / 256, thr>>>(xid, biou);

    // Internal levels, bottom-up.
    for (int lvl = DEPTH - 1; lvl >= 0; lvl--) {
        int M  = 1 << lvl;
        int s  = M - 1;
        int cs = 2 * M - 1;
        k_pairsum<<<(M * HS + 255) / 256, thr>>>(cs, M);
        k_sgemm<<<gemm_grid(M, HS3), thr>>>(phsum, Uiou, phiou, M, HS3, HS);
        k_sgemm<<<gemm_grid(2 * M, HS), thr>>>(ph + (size_t)cs * HS, Uf, phUf, 2 * M, HS, HS);
        k_combine<<<(M * HS + 255) / 256, thr>>>(s, cs, M, xid, biou, bf);
    }

    // Output projection for all nodes.
    k_out<<<(NNODES + 7) / 8, thr>>>(Wout, bout, out);
}

// round 3
// speedup vs baseline: 1.3871x; 1.3871x over previous
#include <cuda_runtime.h>
#include <cuda_bf16.h>
#include <cstdint>
#include <cstddef>

#define VOCAB   50000
#define XS      300
#define HS      150
#define HS3     450
#define NPACK   600          // [iou(450) | f(150)]
#define NC      5
#define DEPTH   18
#define NNODES  524287
#define LEAVES  262144
#define KPAD_W  320          // XS=300 padded (32-mult)
#define KPAD_U  160          // HS=150 padded (32-mult)

// ---------------- static device scratch (no allocation allowed) ------------------
__device__ float g_EW[(size_t)VOCAB * NPACK];            // emb @ [W_iou|W_f]
__device__ float g_hiou[(size_t)(LEAVES / 2) * HS3];     // pairsum(h) @ U_iou
__device__ float g_hUf[(size_t)LEAVES * HS];             // child h @ U_f
__device__ float g_h[(size_t)NNODES * HS];
__device__ float g_c[(size_t)NNODES * HS];
__device__ __nv_bfloat16 g_Bw_hi[(size_t)NPACK * KPAD_W];
__device__ __nv_bfloat16 g_Bw_lo[(size_t)NPACK * KPAD_W];
__device__ __nv_bfloat16 g_Bu_hi[(size_t)NPACK * KPAD_U];
__device__ __nv_bfloat16 g_Bu_lo[(size_t)NPACK * KPAD_U];

// ---------------- FMA-only activations -------------------------------------------
__device__ __forceinline__ float sig_f(float x) {
    float ax = fabsf(x);
    if (ax > 1.0f) return 1.0f / (1.0f + __expf(-x));
    float x2 = x * x;
    float p = fmaf(x2, 2.1357958e-5f, -2.1081349e-4f);
    p = fmaf(x2, p, 2.0833333e-3f);
    p = fmaf(x2, p, -2.0833333e-2f);
    p = fmaf(x2, p, 0.25f);
    return fmaf(x, p, 0.5f);
}
__device__ __forceinline__ float tanh_f(float x) {
    float ax = fabsf(x);
    if (ax > 0.55f) {
        float t = __expf(-2.0f * ax);
        float r = __fdividef(1.0f - t, 1.0f + t);
        return x < 0.0f ? -r : r;
    }
    float x2 = x * x;
    float p = fmaf(x2, 2.1869488e-2f, -5.3968254e-2f);
    p = fmaf(x2, p, 1.3333333e-1f);
    p = fmaf(x2, p, -3.3333333e-1f);
    p = fmaf(x2, p, 1.0f);
    return x * p;
}

// ---------------- weight prep: pack + transpose + bf16 hi/lo split ---------------
// Bw: [600 n][320 k] from [W_iou|W_f] (k = XS). Bu: [600 n][160 k] (k = HS).
__global__ void k_prep(const float* __restrict__ Wiou, const float* __restrict__ Wf,
                       const float* __restrict__ Uiou, const float* __restrict__ Uf)
{
    int idx = blockIdx.x * blockDim.x + threadIdx.x;
    const int NW = NPACK * KPAD_W;
    const int NU = NPACK * KPAD_U;
    if (idx < NW) {
        int n = idx / KPAD_W, k = idx - n * KPAD_W;
        float v = 0.0f;
        if (k < XS) v = (n < HS3) ? Wiou[k * HS3 + n] : Wf[k * HS + (n - HS3)];
        __nv_bfloat16 h = __float2bfloat16_rn(v);
        g_Bw_hi[idx] = h;
        g_Bw_lo[idx] = __float2bfloat16_rn(v - __bfloat162float(h));
    } else if (idx < NW + NU) {
        int j = idx - NW;
        int n = j / KPAD_U, k = j - n * KPAD_U;
        float v = 0.0f;
        if (k < HS) v = (n < HS3) ? Uiou[k * HS3 + n] : Uf[k * HS + (n - HS3)];
        __nv_bfloat16 h = __float2bfloat16_rn(v);
        g_Bu_hi[j] = h;
        g_Bu_lo[j] = __float2bfloat16_rn(v - __bfloat162float(h));
    }
}

// ---------------- mma.sync bf16x3-split GEMM -------------------------------------
// C[M,Nact] = A[M,K] @ B^T   (B stored [n][Kpad] bf16 hi/lo, pre-split)
// PAIR=1: logical A row i = A[2i] + A[2i+1] (fused child pair-sum).
// CTA tile 128x128, 8 warps of 32x64, k-chunks of 32.

#define MMA_BF16(d, a0, a1, a2, a3, b0, b1)                                      \
    asm volatile("mma.sync.aligned.m16n8k16.row.col.f32.bf16.bf16.f32 "          \
                 "{%0,%1,%2,%3},{%4,%5,%6,%7},{%8,%9},{%0,%1,%2,%3};"            \
                 : "+f"(d[0]), "+f"(d[1]), "+f"(d[2]), "+f"(d[3])                \
                 : "r"(a0), "r"(a1), "r"(a2), "r"(a3), "r"(b0), "r"(b1))

#define SROW 20   // u32 per smem row (32 k-halves = 16 u32 + 4 pad) -> 80B stride

template <int PAIR>
__global__ __launch_bounds__(256)
void k_mma(const float* __restrict__ A, int M, int K, int Kpad,
           const __nv_bfloat16* __restrict__ Bhi, const __nv_bfloat16* __restrict__ Blo,
           int Nact, float* __restrict__ C, int ldc)
{
    __shared__ uint32_t sAh[128 * SROW], sAl[128 * SROW];
    __shared__ uint32_t sBh[128 * SROW], sBl[128 * SROW];

    const int tid  = threadIdx.x;
    const int lane = tid & 31;
    const int wid  = tid >> 5;
    const int row0 = blockIdx.y << 7;
    const int col0 = blockIdx.x << 7;
    const int m0 = (wid & 3) << 5;     // warp row offset (32)
    const int n0 = (wid >> 2) << 6;    // warp col offset (64)
    const int g   = lane >> 2;         // 0..7
    const int tig = lane & 3;          // 0..3

    float d[2][8][4];
    #pragma unroll
    for (int mb = 0; mb < 2; mb++)
        #pragma unroll
        for (int nb = 0; nb < 8; nb++)
            #pragma unroll
            for (int q = 0; q < 4; q++) d[mb][nb][q] = 0.0f;

    const int chunks = Kpad >> 5;
    for (int c = 0; c < chunks; c++) {
        const int kb = c << 5;
        // ---- stage A (fp32 -> hi/lo bf16) and B (pre-split) into smem --------
        #pragma unroll
        for (int i = 0; i < 8; i++) {
            int idx = tid + (i << 8);
            int r = idx >> 4, kp = idx & 15;
            int gc = kb + (kp << 1);
            // A
            int gr = row0 + r;
            float v0 = 0.0f, v1 = 0.0f;
            if (gr < M && gc < K) {
                if (PAIR) {
                    const float* p0 = A + (size_t)(2 * gr) * K + gc;
                    float2 u = *(const float2*)p0;
                    float2 w = *(const float2*)(p0 + K);
                    v0 = u.x + w.x; v1 = u.y + w.y;
                } else {
                    float2 u = *(const float2*)(A + (size_t)gr * K + gc);
                    v0 = u.x; v1 = u.y;
                }
            }
            __nv_bfloat16 h0 = __float2bfloat16_rn(v0), h1 = __float2bfloat16_rn(v1);
            __nv_bfloat16 l0 = __float2bfloat16_rn(v0 - __bfloat162float(h0));
            __nv_bfloat16 l1 = __float2bfloat16_rn(v1 - __bfloat162float(h1));
            sAh[r * SROW + kp] = ((uint32_t)__bfloat16_as_ushort(h1) << 16) | __bfloat16_as_ushort(h0);
            sAl[r * SROW + kp] = ((uint32_t)__bfloat16_as_ushort(l1) << 16) | __bfloat16_as_ushort(l0);
            // B
            int gn = col0 + r;
            uint32_t vh = 0, vl = 0;
            if (gn < Nact) {
                size_t gi = (size_t)gn * Kpad + gc;
                vh = *(const uint32_t*)(Bhi + gi);
                vl = *(const uint32_t*)(Blo + gi);
            }
            sBh[r * SROW + kp] = vh;
            sBl[r * SROW + kp] = vl;
        }
        __syncthreads();

        // ---- 2 x k16 MMA steps ----------------------------------------------
        #pragma unroll
        for (int ks = 0; ks < 2; ks++) {
            uint32_t ah[2][4], al[2][4];
            #pragma unroll
            for (int mb = 0; mb < 2; mb++) {
                int base = (m0 + mb * 16 + g) * SROW + ks * 8 + tig;
                ah[mb][0] = sAh[base];
                ah[mb][1] = sAh[base + 8 * SROW];
                ah[mb][2] = sAh[base + 4];
                ah[mb][3] = sAh[base + 8 * SROW + 4];
                al[mb][0] = sAl[base];
                al[mb][1] = sAl[base + 8 * SROW];
                al[mb][2] = sAl[base + 4];
                al[mb][3] = sAl[base + 8 * SROW + 4];
            }
            #pragma unroll
            for (int nb = 0; nb < 8; nb++) {
                int base = (n0 + nb * 8 + g) * SROW + ks * 8 + tig;
                uint32_t bh0 = sBh[base], bh1 = sBh[base + 4];
                uint32_t bl0 = sBl[base], bl1 = sBl[base + 4];
                #pragma unroll
                for (int mb = 0; mb < 2; mb++) {
                    MMA_BF16(d[mb][nb], ah[mb][0], ah[mb][1], ah[mb][2], ah[mb][3], bh0, bh1);
                    MMA_BF16(d[mb][nb], ah[mb][0], ah[mb][1], ah[mb][2], ah[mb][3], bl0, bl1);
                    MMA_BF16(d[mb][nb], al[mb][0], al[mb][1], al[mb][2], al[mb][3], bh0, bh1);
                }
            }
        }
        __syncthreads();
    }

    // ---- epilogue: accumulators -> C --------------------------------------------
    #pragma unroll
    for (int mb = 0; mb < 2; mb++) {
        int gr = row0 + m0 + mb * 16 + g;
        #pragma unroll
        for (int nb = 0; nb < 8; nb++) {
            int gc = col0 + n0 + nb * 8 + tig * 2;
            if (gc < Nact) {
                if (gr < M)
                    *(float2*)(C + (size_t)gr * ldc + gc) = make_float2(d[mb][nb][0], d[mb][nb][1]);
                if (gr + 8 < M)
                    *(float2*)(C + (size_t)(gr + 8) * ldc + gc) = make_float2(d[mb][nb][2], d[mb][nb][3]);
            }
        }
    }
}

// ---------------- leaf level ------------------------------------------------------
__global__ void k_leaf(const int* __restrict__ xid, const float* __restrict__ biou)
{
    int idx = blockIdx.x * blockDim.x + threadIdx.x;
    if (idx >= LEAVES * HS) return;
    int i = idx / HS;
    int j = idx - i * HS;
    int n = (LEAVES - 1) + i;
    const float* ew = g_EW + (size_t)xid[n] * NPACK;
    float iv = ew[j] + biou[j];
    float ov = ew[HS + j] + biou[HS + j];
    float uv = ew[2 * HS + j] + biou[2 * HS + j];
    float cv = sig_f(iv) * tanh_f(uv);
    float hv = sig_f(ov) * tanh_f(cv);
    size_t o = (size_t)n * HS + j;
    g_c[o] = cv;
    g_h[o] = hv;
}

// ---------------- internal-level gate combine ------------------------------------
__global__ void k_combine(int s, int cs, int M, const int* __restrict__ xid,
                          const float* __restrict__ biou, const float* __restrict__ bf)
{
    int idx = blockIdx.x * blockDim.x + threadIdx.x;
    if (idx >= M * HS) return;
    int k = idx / HS;
    int j = idx - k * HS;
    int p = s + k;
    const float* ew  = g_EW + (size_t)xid[p] * NPACK;
    const float* hio = g_hiou + (size_t)k * HS3;

    float iv = ew[j]          + hio[j]          + biou[j];
    float ov = ew[HS + j]     + hio[HS + j]     + biou[HS + j];
    float uv = ew[2 * HS + j] + hio[2 * HS + j] + biou[2 * HS + j];
    float xf = ew[HS3 + j] + bf[j];
    float fl = sig_f(xf + g_hUf[(size_t)(2 * k) * HS + j]);
    float fr = sig_f(xf + g_hUf[(size_t)(2 * k + 1) * HS + j]);
    float cl = g_c[(size_t)(cs + 2 * k) * HS + j];
    float cr = g_c[(size_t)(cs + 2 * k + 1) * HS + j];

    float cv = sig_f(iv) * tanh_f(uv) + fl * cl + fr * cr;
    float hv = sig_f(ov) * tanh_f(cv);
    size_t o = (size_t)p * HS + j;
    g_c[o] = cv;
    g_h[o] = hv;
}

// ---------------- output projection ----------------------------------------------
__global__ void k_out(const float* __restrict__ Wout, const float* __restrict__ bout,
                      float* __restrict__ out)
{
    __shared__ float sW[HS * NC];
    for (int i = threadIdx.x; i < HS * NC; i += blockDim.x) sW[i] = Wout[i];
    __syncthreads();
    int gw = (blockIdx.x * blockDim.x + threadIdx.x) >> 5;
    int lane = threadIdx.x & 31;
    if (gw >= NNODES) return;
    const float* h = g_h + (size_t)gw * HS;
    float a0 = 0.f, a1 = 0.f, a2 = 0.f, a3 = 0.f, a4 = 0.f;
    for (int j = lane; j < HS; j += 32) {
        float hv = h[j];
        const float* w = sW + j * NC;
        a0 = fmaf(hv, w[0], a0);
        a1 = fmaf(hv, w[1], a1);
        a2 = fmaf(hv, w[2], a2);
        a3 = fmaf(hv, w[3], a3);
        a4 = fmaf(hv, w[4], a4);
    }
    #pragma unroll
    for (int off = 16; off; off >>= 1) {
        a0 += __shfl_xor_sync(0xffffffffu, a0, off);
        a1 += __shfl_xor_sync(0xffffffffu, a1, off);
        a2 += __shfl_xor_sync(0xffffffffu, a2, off);
        a3 += __shfl_xor_sync(0xffffffffu, a3, off);
        a4 += __shfl_xor_sync(0xffffffffu, a4, off);
    }
    if (lane == 0) {
        float* o = out + (size_t)gw * NC;
        o[0] = a0 + bout[0]; o[1] = a1 + bout[1]; o[2] = a2 + bout[2];
        o[3] = a3 + bout[3]; o[4] = a4 + bout[4];
    }
}

// ---------------- host orchestration ---------------------------------------------
extern "C" void kernel_launch(void* const* d_in, const int* in_sizes, int n_in,
                              void* d_out, int out_size)
{
    (void)in_sizes; (void)n_in; (void)out_size;
    const int*   xid  = (const int*)d_in[0];
    const float* emb  = (const float*)d_in[1];
    const float* Wiou = (const float*)d_in[2];
    const float* Uiou = (const float*)d_in[3];
    const float* biou = (const float*)d_in[4];
    const float* Wf   = (const float*)d_in[5];
    const float* Uf   = (const float*)d_in[6];
    const float* bf   = (const float*)d_in[7];
    const float* Wout = (const float*)d_in[8];
    const float* bout = (const float*)d_in[9];
    float* out = (float*)d_out;

    float *pEW, *pHiou, *pHUf, *ph;
    __nv_bfloat16 *pBwh, *pBwl, *pBuh, *pBul;
    cudaGetSymbolAddress((void**)&pEW,   g_EW);
    cudaGetSymbolAddress((void**)&pHiou, g_hiou);
    cudaGetSymbolAddress((void**)&pHUf,  g_hUf);
    cudaGetSymbolAddress((void**)&ph,    g_h);
    cudaGetSymbolAddress((void**)&pBwh,  g_Bw_hi);
    cudaGetSymbolAddress((void**)&pBwl,  g_Bw_lo);
    cudaGetSymbolAddress((void**)&pBuh,  g_Bu_hi);
    cudaGetSymbolAddress((void**)&pBul,  g_Bu_lo);

    const dim3 thr(256);
    const int prep_total = NPACK * KPAD_W + NPACK * KPAD_U;
    k_prep<<<(prep_total + 255) / 256, thr>>>(Wiou, Wf, Uiou, Uf);

    // Vocab precompute: g_EW = emb @ [W_iou | W_f]   (50000 x 600, K=300)
    k_mma<0><<<dim3(5, (VOCAB + 127) / 128), thr>>>(
        emb, VOCAB, XS, KPAD_W, pBwh, pBwl, NPACK, pEW, NPACK);

    k_leaf<<<(LEAVES * HS + 255) / 256, thr>>>(xid, biou);

    for (int lvl = DEPTH - 1; lvl >= 0; lvl--) {
        int M  = 1 << lvl;
        int s  = M - 1;
        int cs = 2 * M - 1;
        // pairsum(h children) @ U_iou  -> g_hiou [M x 450]
        k_mma<1><<<dim3(4, (M + 127) / 128), thr>>>(
            ph + (size_t)cs * HS, M, HS, KPAD_U, pBuh, pBul, HS3, pHiou, HS3);
        // h children @ U_f -> g_hUf [2M x 150]   (B rows 450..599 of packed Bu)
        k_mma<0><<<dim3(2, (2 * M + 127) / 128), thr>>>(
            ph + (size_t)cs * HS, 2 * M, HS, KPAD_U,
            pBuh + (size_t)HS3 * KPAD_U, pBul + (size_t)HS3 * KPAD_U, HS, pHUf, HS);
        k_combine<<<(M * HS + 255) / 256, thr>>>(s, cs, M, xid, biou, bf);
    }

    k_out<<<(NNODES + 7) / 8, thr>>>(Wout, bout, out);
}

// round 4
// speedup vs baseline: 1.8615x; 1.3420x over previous
#include <cuda_runtime.h>
#include <cuda_bf16.h>
#include <cstdint>
#include <cstddef>

#define VOCAB   50000
#define VPAD    50048        // 391 * 128
#define XS      300
#define HS      150
#define HS3     450
#define NPACK   600          // [iou(450) | f(150)]
#define NBROW   768          // padded B rows (tile-safe overreach)
#define NC      5
#define DEPTH   18
#define NNODES  524287
#define LEAVES  262144
#define KPW     320          // XS padded
#define KPU     160          // HS padded

// ---------------- static device scratch ------------------------------------------
__device__ float g_EW[(size_t)VOCAB * NPACK];
__device__ float g_hiou[(size_t)(LEAVES / 2) * HS3];
__device__ float g_hUf[(size_t)LEAVES * HS];
__device__ float g_c[(size_t)NNODES * HS];
__device__ __nv_bfloat16 g_hhi[(size_t)(NNODES + 128) * KPU];
__device__ __nv_bfloat16 g_hlo[(size_t)(NNODES + 128) * KPU];
__device__ __nv_bfloat16 g_shi[(size_t)(LEAVES / 2) * KPU];
__device__ __nv_bfloat16 g_slo[(size_t)(LEAVES / 2) * KPU];
__device__ __nv_bfloat16 g_Ehi[(size_t)VPAD * KPW];
__device__ __nv_bfloat16 g_Elo[(size_t)VPAD * KPW];
__device__ __nv_bfloat16 g_Bwh[(size_t)NBROW * KPW];
__device__ __nv_bfloat16 g_Bwl[(size_t)NBROW * KPW];
__device__ __nv_bfloat16 g_Buh[(size_t)NBROW * KPU];
__device__ __nv_bfloat16 g_Bul[(size_t)NBROW * KPU];

// ---------------- helpers ---------------------------------------------------------
__device__ __forceinline__ uint32_t smem_u32(const void* p) {
    uint32_t a;
    asm("{ .reg .u64 t; cvta.to.shared.u64 t, %1; cvt.u32.u64 %0, t; }" : "=r"(a) : "l"(p));
    return a;
}
__device__ __forceinline__ void split2(float v, __nv_bfloat16& h, __nv_bfloat16& l) {
    h = __float2bfloat16_rn(v);
    l = __float2bfloat16_rn(v - __bfloat162float(h));
}
#define CP16(dst, src) \
    asm volatile("cp.async.cg.shared.global [%0], [%1], 16;" :: "r"(dst), "l"(src))
#define CP_COMMIT() asm volatile("cp.async.commit_group;" ::: "memory")
#define CP_WAIT1()  asm volatile("cp.async.wait_group 1;" ::: "memory")
#define CP_WAIT0()  asm volatile("cp.async.wait_group 0;" ::: "memory")

// ---------------- FMA-only activations -------------------------------------------
__device__ __forceinline__ float sig_f(float x) {
    float ax = fabsf(x);
    if (ax > 1.0f) return 1.0f / (1.0f + __expf(-x));
    float x2 = x * x;
    float p = fmaf(x2, 2.1357958e-5f, -2.1081349e-4f);
    p = fmaf(x2, p, 2.0833333e-3f);
    p = fmaf(x2, p, -2.0833333e-2f);
    p = fmaf(x2, p, 0.25f);
    return fmaf(x, p, 0.5f);
}
__device__ __forceinline__ float tanh_f(float x) {
    float ax = fabsf(x);
    if (ax > 0.55f) {
        float t = __expf(-2.0f * ax);
        float r = __fdividef(1.0f - t, 1.0f + t);
        return x < 0.0f ? -r : r;
    }
    float x2 = x * x;
    float p = fmaf(x2, 2.1869488e-2f, -5.3968254e-2f);
    p = fmaf(x2, p, 1.3333333e-1f);
    p = fmaf(x2, p, -3.3333333e-1f);
    p = fmaf(x2, p, 1.0f);
    return x * p;
}

// ---------------- prep: weights pack+transpose+split (rows padded to NBROW) ------
__global__ void k_prep_w(const float* __restrict__ Wiou, const float* __restrict__ Wf,
                         const float* __restrict__ Uiou, const float* __restrict__ Uf)
{
    int idx = blockIdx.x * blockDim.x + threadIdx.x;
    const int NW = NBROW * KPW;
    const int NU = NBROW * KPU;
    if (idx < NW) {
        int n = idx / KPW, k = idx - n * KPW;
        float v = 0.0f;
        if (k < XS && n < NPACK) v = (n < HS3) ? Wiou[k * HS3 + n] : Wf[k * HS + (n - HS3)];
        split2(v, g_Bwh[idx], g_Bwl[idx]);
    } else if (idx < NW + NU) {
        int j = idx - NW;
        int n = j / KPU, k = j - n * KPU;
        float v = 0.0f;
        if (k < HS && n < NPACK) v = (n < HS3) ? Uiou[k * HS3 + n] : Uf[k * HS + (n - HS3)];
        split2(v, g_Buh[j], g_Bul[j]);
    }
}

// ---------------- prep: emb -> padded bf16 hi/lo ---------------------------------
__global__ void k_prep_emb(const float* __restrict__ emb)
{
    int idx = blockIdx.x * blockDim.x + threadIdx.x;
    if (idx >= VPAD * KPW) return;
    int r = idx / KPW, k = idx - r * KPW;
    float v = (r < VOCAB && k < XS) ? emb[(size_t)r * XS + k] : 0.0f;
    split2(v, g_Ehi[idx], g_Elo[idx]);
}

// ---------------- prep: zero k-pad columns of h/psum split buffers ---------------
__global__ void k_zeropads()
{
    int idx = blockIdx.x * blockDim.x + threadIdx.x;
    const int T1 = (NNODES + 128) * 10;
    const int T2 = (LEAVES / 2) * 10;
    if (idx < T1) {
        int r = idx / 10, k = HS + idx % 10;
        g_hhi[(size_t)r * KPU + k] = __nv_bfloat16(0.0f);
        g_hlo[(size_t)r * KPU + k] = __nv_bfloat16(0.0f);
    } else if (idx < T1 + T2) {
        int j = idx - T1;
        int r = j / 10, k = HS + j % 10;
        g_shi[(size_t)r * KPU + k] = __nv_bfloat16(0.0f);
        g_slo[(size_t)r * KPU + k] = __nv_bfloat16(0.0f);
    }
}

// ---------------- cp.async double-buffered bf16x3-split mma.sync GEMM ------------
// C[M,Nact] = A @ B^T ; A,B pre-split bf16 [row][Kpad]; CTA 128x128, 8 warps 32x64.
#define MMA_BF16(d, a0, a1, a2, a3, b0, b1)                                      \
    asm volatile("mma.sync.aligned.m16n8k16.row.col.f32.bf16.bf16.f32 "          \
                 "{%0,%1,%2,%3},{%4,%5,%6,%7},{%8,%9},{%0,%1,%2,%3};"            \
                 : "+f"(d[0]), "+f"(d[1]), "+f"(d[2]), "+f"(d[3])                \
                 : "r"(a0), "r"(a1), "r"(a2), "r"(a3), "r"(b0), "r"(b1))

#define SROW   20                    // u32 per smem row (64B data + 16B pad)
#define PLANEB 10240                 // 128 * 80 bytes
#define STAGEB 40960                 // 4 planes
#define SMEMT  81920                 // 2 stages

__global__ __launch_bounds__(256)
void k_mma(const __nv_bfloat16* __restrict__ Ahi, const __nv_bfloat16* __restrict__ Alo,
           int M, int Kpad,
           const __nv_bfloat16* __restrict__ Bhi, const __nv_bfloat16* __restrict__ Blo,
           int Nact, float* __restrict__ C, int ldc)
{
    extern __shared__ char smem[];
    const uint32_t sb = smem_u32(smem);
    const int tid  = threadIdx.x;
    const int lane = tid & 31;
    const int wid  = tid >> 5;
    const int row0 = blockIdx.y << 7;
    const int col0 = blockIdx.x << 7;
    const int m0 = (wid & 3) << 5;
    const int n0 = (wid >> 2) << 6;
    const int g   = lane >> 2;
    const int tig = lane & 3;

    const char* pA_h = (const char*)(Ahi + (size_t)row0 * Kpad);
    const char* pA_l = (const char*)(Alo + (size_t)row0 * Kpad);
    const char* pB_h = (const char*)(Bhi + (size_t)col0 * Kpad);
    const char* pB_l = (const char*)(Blo + (size_t)col0 * Kpad);

    const int r_ld  = tid >> 1;                 // 0..127 (rows, 2 threads each)
    const int sg2   = (tid & 1) << 1;           // segment pair 0 or 2

    float d[2][8][4];
    #pragma unroll
    for (int mb = 0; mb < 2; mb++)
        #pragma unroll
        for (int nb = 0; nb < 8; nb++)
            #pragma unroll
            for (int q = 0; q < 4; q++) d[mb][nb][q] = 0.0f;

    // loader: each thread copies 2x16B per plane (8 cp.async total per chunk)
    auto load_chunk = [&](int kb, int st) {
        uint32_t dbase = sb + st * STAGEB + r_ld * 80 + sg2 * 16;
        size_t   soff  = ((size_t)r_ld * Kpad + kb + sg2 * 8) * 2;
        CP16(dbase,              pA_h + soff);
        CP16(dbase + 16,         pA_h + soff + 16);
        CP16(dbase + PLANEB,     pA_l + soff);
        CP16(dbase + PLANEB + 16, pA_l + soff + 16);
        CP16(dbase + 2 * PLANEB, pB_h + soff);
        CP16(dbase + 2 * PLANEB + 16, pB_h + soff + 16);
        CP16(dbase + 3 * PLANEB, pB_l + soff);
        CP16(dbase + 3 * PLANEB + 16, pB_l + soff + 16);
    };

    const int chunks = Kpad >> 5;
    load_chunk(0, 0);
    CP_COMMIT();

    for (int c = 0; c < chunks; c++) {
        if (c + 1 < chunks) {
            load_chunk((c + 1) << 5, (c + 1) & 1);
            CP_COMMIT();
            CP_WAIT1();
        } else {
            CP_WAIT0();
        }
        __syncthreads();

        const uint32_t* sAh = (const uint32_t*)(smem + (c & 1) * STAGEB);
        const uint32_t* sAl = sAh + PLANEB / 4;
        const uint32_t* sBh = sAh + 2 * PLANEB / 4;
        const uint32_t* sBl = sAh + 3 * PLANEB / 4;

        #pragma unroll
        for (int ks = 0; ks < 2; ks++) {
            uint32_t ah[2][4], al[2][4];
            #pragma unroll
            for (int mb = 0; mb < 2; mb++) {
                int base = (m0 + mb * 16 + g) * SROW + ks * 8 + tig;
                ah[mb][0] = sAh[base];
                ah[mb][1] = sAh[base + 8 * SROW];
                ah[mb][2] = sAh[base + 4];
                ah[mb][3] = sAh[base + 8 * SROW + 4];
                al[mb][0] = sAl[base];
                al[mb][1] = sAl[base + 8 * SROW];
                al[mb][2] = sAl[base + 4];
                al[mb][3] = sAl[base + 8 * SROW + 4];
            }
            #pragma unroll
            for (int nb = 0; nb < 8; nb++) {
                int base = (n0 + nb * 8 + g) * SROW + ks * 8 + tig;
                uint32_t bh0 = sBh[base], bh1 = sBh[base + 4];
                uint32_t bl0 = sBl[base], bl1 = sBl[base + 4];
                #pragma unroll
                for (int mb = 0; mb < 2; mb++) {
                    MMA_BF16(d[mb][nb], ah[mb][0], ah[mb][1], ah[mb][2], ah[mb][3], bh0, bh1);
                    MMA_BF16(d[mb][nb], ah[mb][0], ah[mb][1], ah[mb][2], ah[mb][3], bl0, bl1);
                    MMA_BF16(d[mb][nb], al[mb][0], al[mb][1], al[mb][2], al[mb][3], bh0, bh1);
                }
            }
        }
        __syncthreads();
    }

    #pragma unroll
    for (int mb = 0; mb < 2; mb++) {
        int gr = row0 + m0 + mb * 16 + g;
        #pragma unroll
        for (int nb = 0; nb < 8; nb++) {
            int gc = col0 + n0 + nb * 8 + tig * 2;
            if (gc < Nact) {
                if (gr < M)
                    *(float2*)(C + (size_t)gr * ldc + gc) = make_float2(d[mb][nb][0], d[mb][nb][1]);
                if (gr + 8 < M)
                    *(float2*)(C + (size_t)(gr + 8) * ldc + gc) = make_float2(d[mb][nb][2], d[mb][nb][3]);
            }
        }
    }
}

// ---------------- pair-sum of children h -> split bf16 ---------------------------
__global__ void k_psum(int cs, int M)
{
    int idx = blockIdx.x * blockDim.x + threadIdx.x;
    if (idx >= M * HS) return;
    int k = idx / HS;
    int j = idx - k * HS;
    size_t c0 = (size_t)(cs + 2 * k) * KPU + j;
    float s = __bfloat162float(g_hhi[c0]) + __bfloat162float(g_hlo[c0])
            + __bfloat162float(g_hhi[c0 + KPU]) + __bfloat162float(g_hlo[c0 + KPU]);
    size_t o = (size_t)k * KPU + j;
    split2(s, g_shi[o], g_slo[o]);
}

// ---------------- leaf level ------------------------------------------------------
__global__ void k_leaf(const int* __restrict__ xid, const float* __restrict__ biou)
{
    int idx = blockIdx.x * blockDim.x + threadIdx.x;
    if (idx >= LEAVES * HS) return;
    int i = idx / HS;
    int j = idx - i * HS;
    int n = (LEAVES - 1) + i;
    const float* ew = g_EW + (size_t)xid[n] * NPACK;
    float iv = ew[j] + biou[j];
    float ov = ew[HS + j] + biou[HS + j];
    float uv = ew[2 * HS + j] + biou[2 * HS + j];
    float cv = sig_f(iv) * tanh_f(uv);
    float hv = sig_f(ov) * tanh_f(cv);
    g_c[(size_t)n * HS + j] = cv;
    size_t o = (size_t)n * KPU + j;
    split2(hv, g_hhi[o], g_hlo[o]);
}

// ---------------- internal-level gate combine ------------------------------------
__global__ void k_combine(int s, int cs, int M, const int* __restrict__ xid,
                          const float* __restrict__ biou, const float* __restrict__ bf)
{
    int idx = blockIdx.x * blockDim.x + threadIdx.x;
    if (idx >= M * HS) return;
    int k = idx / HS;
    int j = idx - k * HS;
    int p = s + k;
    const float* ew  = g_EW + (size_t)xid[p] * NPACK;
    const float* hio = g_hiou + (size_t)k * HS3;

    float iv = ew[j]          + hio[j]          + biou[j];
    float ov = ew[HS + j]     + hio[HS + j]     + biou[HS + j];
    float uv = ew[2 * HS + j] + hio[2 * HS + j] + biou[2 * HS + j];
    float xf = ew[HS3 + j] + bf[j];
    float fl = sig_f(xf + g_hUf[(size_t)(2 * k) * HS + j]);
    float fr = sig_f(xf + g_hUf[(size_t)(2 * k + 1) * HS + j]);
    float cl = g_c[(size_t)(cs + 2 * k) * HS + j];
    float cr = g_c[(size_t)(cs + 2 * k + 1) * HS + j];

    float cv = sig_f(iv) * tanh_f(uv) + fl * cl + fr * cr;
    float hv = sig_f(ov) * tanh_f(cv);
    g_c[(size_t)p * HS + j] = cv;
    size_t o = (size_t)p * KPU + j;
    split2(hv, g_hhi[o], g_hlo[o]);
}

// ---------------- output projection ----------------------------------------------
__global__ void k_out(const float* __restrict__ Wout, const float* __restrict__ bout,
                      float* __restrict__ out)
{
    __shared__ float sW[HS * NC];
    for (int i = threadIdx.x; i < HS * NC; i += blockDim.x) sW[i] = Wout[i];
    __syncthreads();
    int gw = (blockIdx.x * blockDim.x + threadIdx.x) >> 5;
    int lane = threadIdx.x & 31;
    if (gw >= NNODES) return;
    const __nv_bfloat16* hh = g_hhi + (size_t)gw * KPU;
    const __nv_bfloat16* hl = g_hlo + (size_t)gw * KPU;
    float a0 = 0.f, a1 = 0.f, a2 = 0.f, a3 = 0.f, a4 = 0.f;
    for (int j = lane; j < HS; j += 32) {
        float hv = __bfloat162float(hh[j]) + __bfloat162float(hl[j]);
        const float* w = sW + j * NC;
        a0 = fmaf(hv, w[0], a0);
        a1 = fmaf(hv, w[1], a1);
        a2 = fmaf(hv, w[2], a2);
        a3 = fmaf(hv, w[3], a3);
        a4 = fmaf(hv, w[4], a4);
    }
    #pragma unroll
    for (int off = 16; off; off >>= 1) {
        a0 += __shfl_xor_sync(0xffffffffu, a0, off);
        a1 += __shfl_xor_sync(0xffffffffu, a1, off);
        a2 += __shfl_xor_sync(0xffffffffu, a2, off);
        a3 += __shfl_xor_sync(0xffffffffu, a3, off);
        a4 += __shfl_xor_sync(0xffffffffu, a4, off);
    }
    if (lane == 0) {
        float* o = out + (size_t)gw * NC;
        o[0] = a0 + bout[0]; o[1] = a1 + bout[1]; o[2] = a2 + bout[2];
        o[3] = a3 + bout[3]; o[4] = a4 + bout[4];
    }
}

// ---------------- host orchestration ---------------------------------------------
extern "C" void kernel_launch(void* const* d_in, const int* in_sizes, int n_in,
                              void* d_out, int out_size)
{
    (void)in_sizes; (void)n_in; (void)out_size;
    const int*   xid  = (const int*)d_in[0];
    const float* emb  = (const float*)d_in[1];
    const float* Wiou = (const float*)d_in[2];
    const float* Uiou = (const float*)d_in[3];
    const float* biou = (const float*)d_in[4];
    const float* Wf   = (const float*)d_in[5];
    const float* Uf   = (const float*)d_in[6];
    const float* bf   = (const float*)d_in[7];
    const float* Wout = (const float*)d_in[8];
    const float* bout = (const float*)d_in[9];
    float* out = (float*)d_out;

    float *pEW, *pHiou, *pHUf;
    __nv_bfloat16 *pEhi, *pElo, *pBwh, *pBwl, *pBuh, *pBul, *pHhi, *pHlo, *pShi, *pSlo;
    cudaGetSymbolAddress((void**)&pEW,   g_EW);
    cudaGetSymbolAddress((void**)&pHiou, g_hiou);
    cudaGetSymbolAddress((void**)&pHUf,  g_hUf);
    cudaGetSymbolAddress((void**)&pEhi,  g_Ehi);
    cudaGetSymbolAddress((void**)&pElo,  g_Elo);
    cudaGetSymbolAddress((void**)&pBwh,  g_Bwh);
    cudaGetSymbolAddress((void**)&pBwl,  g_Bwl);
    cudaGetSymbolAddress((void**)&pBuh,  g_Buh);
    cudaGetSymbolAddress((void**)&pBul,  g_Bul);
    cudaGetSymbolAddress((void**)&pHhi,  g_hhi);
    cudaGetSymbolAddress((void**)&pHlo,  g_hlo);
    cudaGetSymbolAddress((void**)&pShi,  g_shi);
    cudaGetSymbolAddress((void**)&pSlo,  g_slo);

    cudaFuncSetAttribute(k_mma, cudaFuncAttributeMaxDynamicSharedMemorySize, SMEMT);

    const dim3 thr(256);
    k_prep_w<<<(NBROW * KPW + NBROW * KPU + 255) / 256, thr>>>(Wiou, Wf, Uiou, Uf);
    k_prep_emb<<<(VPAD * KPW + 255) / 256, thr>>>(emb);
    {
        int zt = (NNODES + 128) * 10 + (LEAVES / 2) * 10;
        k_zeropads<<<(zt + 255) / 256, thr>>>();
    }

    // Vocab precompute: g_EW = emb @ [W_iou | W_f]
    k_mma<<<dim3(5, VPAD / 128), thr, SMEMT>>>(pEhi, pElo, VOCAB, KPW, pBwh, pBwl,
                                               NPACK, pEW, NPACK);

    k_leaf<<<(LEAVES * HS + 255) / 256, thr>>>(xid, biou);

    for (int lvl = DEPTH - 1; lvl >= 0; lvl--) {
        int M  = 1 << lvl;
        int s  = M - 1;
        int cs = 2 * M - 1;
        k_psum<<<(M * HS + 255) / 256, thr>>>(cs, M);
        k_mma<<<dim3(4, (M + 127) / 128), thr, SMEMT>>>(
            pShi, pSlo, M, KPU, pBuh, pBul, HS3, pHiou, HS3);
        k_mma<<<dim3(2, (2 * M + 127) / 128), thr, SMEMT>>>(
            pHhi + (size_t)cs * KPU, pHlo + (size_t)cs * KPU, 2 * M, KPU,
            pBuh + (size_t)HS3 * KPU, pBul + (size_t)HS3 * KPU, HS, pHUf, HS);
        k_combine<<<(M * HS + 255) / 256, thr>>>(s, cs, M, xid, biou, bf);
    }

    k_out<<<(NNODES + 7) / 8, thr>>>(Wout, bout, out);
}

// round 5
// speedup vs baseline: 2.0234x; 1.0870x over previous
#include <cuda_runtime.h>
#include <cuda_bf16.h>
#include <cstdint>
#include <cstddef>

#define VOCAB   50000
#define VPAD    50048        // 391 * 128
#define XS      300
#define HS      150
#define HS3     450
#define NPACK   600          // [iou(450) | f(150)]
#define NBROW   768
#define NC      5
#define DEPTH   18
#define NNODES  524287
#define LEAVES  262144
#define KPW     320
#define KPU     160
#define LVL_SMALL 7          // levels < LVL_SMALL use the fused GEMV path

// ---------------- static device scratch ------------------------------------------
__device__ float g_EW[(size_t)VOCAB * NPACK];
__device__ float g_hiou[(size_t)(LEAVES / 2) * HS3];
__device__ float g_hUf[(size_t)LEAVES * HS];
__device__ float g_c[(size_t)NNODES * HS];
__device__ __nv_bfloat16 g_hhi[(size_t)(NNODES + 128) * KPU];
__device__ __nv_bfloat16 g_hlo[(size_t)(NNODES + 128) * KPU];
__device__ __nv_bfloat16 g_shi[(size_t)(LEAVES / 2) * KPU];
__device__ __nv_bfloat16 g_slo[(size_t)(LEAVES / 2) * KPU];
__device__ __nv_bfloat16 g_Ehi[(size_t)VPAD * KPW];
__device__ __nv_bfloat16 g_Elo[(size_t)VPAD * KPW];
__device__ __nv_bfloat16 g_Bwh[(size_t)NBROW * KPW];
__device__ __nv_bfloat16 g_Bwl[(size_t)NBROW * KPW];
__device__ __nv_bfloat16 g_Buh[(size_t)NBROW * KPU];
__device__ __nv_bfloat16 g_Bul[(size_t)NBROW * KPU];

// ---------------- helpers ---------------------------------------------------------
__device__ __forceinline__ uint32_t smem_u32(const void* p) {
    uint32_t a;
    asm("{ .reg .u64 t; cvta.to.shared.u64 t, %1; cvt.u32.u64 %0, t; }" : "=r"(a) : "l"(p));
    return a;
}
__device__ __forceinline__ void split2(float v, __nv_bfloat16& h, __nv_bfloat16& l) {
    h = __float2bfloat16_rn(v);
    l = __float2bfloat16_rn(v - __bfloat162float(h));
}
#define CP16(dst, src) \
    asm volatile("cp.async.cg.shared.global [%0], [%1], 16;" :: "r"(dst), "l"(src))
#define CP_COMMIT() asm volatile("cp.async.commit_group;" ::: "memory")
#define CP_WAIT1()  asm volatile("cp.async.wait_group 1;" ::: "memory")
#define CP_WAIT0()  asm volatile("cp.async.wait_group 0;" ::: "memory")

// ---------------- FMA-only activations -------------------------------------------
__device__ __forceinline__ float sig_f(float x) {
    float ax = fabsf(x);
    if (ax > 1.0f) return 1.0f / (1.0f + __expf(-x));
    float x2 = x * x;
    float p = fmaf(x2, 2.1357958e-5f, -2.1081349e-4f);
    p = fmaf(x2, p, 2.0833333e-3f);
    p = fmaf(x2, p, -2.0833333e-2f);
    p = fmaf(x2, p, 0.25f);
    return fmaf(x, p, 0.5f);
}
__device__ __forceinline__ float tanh_f(float x) {
    float ax = fabsf(x);
    if (ax > 0.55f) {
        float t = __expf(-2.0f * ax);
        float r = __fdividef(1.0f - t, 1.0f + t);
        return x < 0.0f ? -r : r;
    }
    float x2 = x * x;
    float p = fmaf(x2, 2.1869488e-2f, -5.3968254e-2f);
    p = fmaf(x2, p, 1.3333333e-1f);
    p = fmaf(x2, p, -3.3333333e-1f);
    p = fmaf(x2, p, 1.0f);
    return x * p;
}

// ---------------- prep kernels ----------------------------------------------------
__global__ void k_prep_w(const float* __restrict__ Wiou, const float* __restrict__ Wf,
                         const float* __restrict__ Uiou, const float* __restrict__ Uf)
{
    int idx = blockIdx.x * blockDim.x + threadIdx.x;
    const int NW = NBROW * KPW;
    const int NU = NBROW * KPU;
    if (idx < NW) {
        int n = idx / KPW, k = idx - n * KPW;
        float v = 0.0f;
        if (k < XS && n < NPACK) v = (n < HS3) ? Wiou[k * HS3 + n] : Wf[k * HS + (n - HS3)];
        split2(v, g_Bwh[idx], g_Bwl[idx]);
    } else if (idx < NW + NU) {
        int j = idx - NW;
        int n = j / KPU, k = j - n * KPU;
        float v = 0.0f;
        if (k < HS && n < NPACK) v = (n < HS3) ? Uiou[k * HS3 + n] : Uf[k * HS + (n - HS3)];
        split2(v, g_Buh[j], g_Bul[j]);
    }
}

__global__ void k_prep_emb(const float* __restrict__ emb)
{
    int idx = blockIdx.x * blockDim.x + threadIdx.x;
    if (idx >= VPAD * KPW) return;
    int r = idx / KPW, k = idx - r * KPW;
    float v = (r < VOCAB && k < XS) ? emb[(size_t)r * XS + k] : 0.0f;
    split2(v, g_Ehi[idx], g_Elo[idx]);
}

__global__ void k_zeropads()
{
    int idx = blockIdx.x * blockDim.x + threadIdx.x;
    const int T1 = (NNODES + 128) * 10;
    const int T2 = (LEAVES / 2) * 10;
    if (idx < T1) {
        int r = idx / 10, k = HS + idx % 10;
        g_hhi[(size_t)r * KPU + k] = __nv_bfloat16(0.0f);
        g_hlo[(size_t)r * KPU + k] = __nv_bfloat16(0.0f);
    } else if (idx < T1 + T2) {
        int j = idx - T1;
        int r = j / 10, k = HS + j % 10;
        g_shi[(size_t)r * KPU + k] = __nv_bfloat16(0.0f);
        g_slo[(size_t)r * KPU + k] = __nv_bfloat16(0.0f);
    }
}

// ---------------- cp.async double-buffered bf16x3-split mma.sync GEMM ------------
#define MMA_BF16(d, a0, a1, a2, a3, b0, b1)                                      \
    asm volatile("mma.sync.aligned.m16n8k16.row.col.f32.bf16.bf16.f32 "          \
                 "{%0,%1,%2,%3},{%4,%5,%6,%7},{%8,%9},{%0,%1,%2,%3};"            \
                 : "+f"(d[0]), "+f"(d[1]), "+f"(d[2]), "+f"(d[3])                \
                 : "r"(a0), "r"(a1), "r"(a2), "r"(a3), "r"(b0), "r"(b1))

#define SROW   20
#define PLANEB 10240
#define STAGEB 40960
#define SMEMT  81920

__global__ __launch_bounds__(256, 2)
void k_mma(const __nv_bfloat16* __restrict__ Ahi, const __nv_bfloat16* __restrict__ Alo,
           int M, int Kpad,
           const __nv_bfloat16* __restrict__ Bhi, const __nv_bfloat16* __restrict__ Blo,
           int Nact, float* __restrict__ C, int ldc)
{
    extern __shared__ char smem[];
    const uint32_t sb = smem_u32(smem);
    const int tid  = threadIdx.x;
    const int lane = tid & 31;
    const int wid  = tid >> 5;
    const int row0 = blockIdx.y << 7;
    const int col0 = blockIdx.x << 7;
    const int m0 = (wid & 3) << 5;
    const int n0 = (wid >> 2) << 6;
    const int g   = lane >> 2;
    const int tig = lane & 3;

    const char* pA_h = (const char*)(Ahi + (size_t)row0 * Kpad);
    const char* pA_l = (const char*)(Alo + (size_t)row0 * Kpad);
    const char* pB_h = (const char*)(Bhi + (size_t)col0 * Kpad);
    const char* pB_l = (const char*)(Blo + (size_t)col0 * Kpad);

    const int r_ld  = tid >> 1;
    const int sg2   = (tid & 1) << 1;

    float d[2][8][4];
    #pragma unroll
    for (int mb = 0; mb < 2; mb++)
        #pragma unroll
        for (int nb = 0; nb < 8; nb++)
            #pragma unroll
            for (int q = 0; q < 4; q++) d[mb][nb][q] = 0.0f;

    auto load_chunk = [&](int kb, int st) {
        uint32_t dbase = sb + st * STAGEB + r_ld * 80 + sg2 * 16;
        size_t   soff  = ((size_t)r_ld * Kpad + kb + sg2 * 8) * 2;
        CP16(dbase,               pA_h + soff);
        CP16(dbase + 16,          pA_h + soff + 16);
        CP16(dbase + PLANEB,      pA_l + soff);
        CP16(dbase + PLANEB + 16, pA_l + soff + 16);
        CP16(dbase + 2 * PLANEB,      pB_h + soff);
        CP16(dbase + 2 * PLANEB + 16, pB_h + soff + 16);
        CP16(dbase + 3 * PLANEB,      pB_l + soff);
        CP16(dbase + 3 * PLANEB + 16, pB_l + soff + 16);
    };

    const int chunks = Kpad >> 5;
    load_chunk(0, 0);
    CP_COMMIT();

    for (int c = 0; c < chunks; c++) {
        if (c + 1 < chunks) {
            load_chunk((c + 1) << 5, (c + 1) & 1);
            CP_COMMIT();
            CP_WAIT1();
        } else {
            CP_WAIT0();
        }
        __syncthreads();

        const uint32_t* sAh = (const uint32_t*)(smem + (c & 1) * STAGEB);
        const uint32_t* sAl = sAh + PLANEB / 4;
        const uint32_t* sBh = sAh + 2 * PLANEB / 4;
        const uint32_t* sBl = sAh + 3 * PLANEB / 4;

        #pragma unroll
        for (int ks = 0; ks < 2; ks++) {
            uint32_t ah[2][4], al[2][4];
            #pragma unroll
            for (int mb = 0; mb < 2; mb++) {
                int base = (m0 + mb * 16 + g) * SROW + ks * 8 + tig;
                ah[mb][0] = sAh[base];
                ah[mb][1] = sAh[base + 8 * SROW];
                ah[mb][2] = sAh[base + 4];
                ah[mb][3] = sAh[base + 8 * SROW + 4];
                al[mb][0] = sAl[base];
                al[mb][1] = sAl[base + 8 * SROW];
                al[mb][2] = sAl[base + 4];
                al[mb][3] = sAl[base + 8 * SROW + 4];
            }
            #pragma unroll
            for (int nb = 0; nb < 8; nb++) {
                int base = (n0 + nb * 8 + g) * SROW + ks * 8 + tig;
                uint32_t bh0 = sBh[base], bh1 = sBh[base + 4];
                uint32_t bl0 = sBl[base], bl1 = sBl[base + 4];
                #pragma unroll
                for (int mb = 0; mb < 2; mb++) {
                    MMA_BF16(d[mb][nb], ah[mb][0], ah[mb][1], ah[mb][2], ah[mb][3], bh0, bh1);
                    MMA_BF16(d[mb][nb], ah[mb][0], ah[mb][1], ah[mb][2], ah[mb][3], bl0, bl1);
                    MMA_BF16(d[mb][nb], al[mb][0], al[mb][1], al[mb][2], al[mb][3], bh0, bh1);
                }
            }
        }
        __syncthreads();
    }

    #pragma unroll
    for (int mb = 0; mb < 2; mb++) {
        int gr = row0 + m0 + mb * 16 + g;
        #pragma unroll
        for (int nb = 0; nb < 8; nb++) {
            int gc = col0 + n0 + nb * 8 + tig * 2;
            if (gc < Nact) {
                if (gr < M)
                    *(float2*)(C + (size_t)gr * ldc + gc) = make_float2(d[mb][nb][0], d[mb][nb][1]);
                if (gr + 8 < M)
                    *(float2*)(C + (size_t)(gr + 8) * ldc + gc) = make_float2(d[mb][nb][2], d[mb][nb][3]);
            }
        }
    }
}

// ---------------- leaf level: gates + fused pair-sum ------------------------------
// block = 320 threads (300 active = 2 leaves x 150); writes psum row for lvl 17.
__global__ __launch_bounds__(320)
void k_leaf(const int* __restrict__ xid, const float* __restrict__ biou)
{
    __shared__ float sh[300];
    const int t = threadIdx.x;
    const int b = blockIdx.x;
    if (t < 300) {
        int child = (t >= 150);
        int j = t - child * 150;
        int i = 2 * b + child;
        int n = (LEAVES - 1) + i;
        const float* ew = g_EW + (size_t)xid[n] * NPACK;
        float iv = ew[j] + biou[j];
        float ov = ew[HS + j] + biou[HS + j];
        float uv = ew[2 * HS + j] + biou[2 * HS + j];
        float cv = sig_f(iv) * tanh_f(uv);
        float hv = sig_f(ov) * tanh_f(cv);
        g_c[(size_t)n * HS + j] = cv;
        size_t o = (size_t)n * KPU + j;
        split2(hv, g_hhi[o], g_hlo[o]);
        sh[t] = hv;
    }
    __syncthreads();
    if (t < 150) {
        float s = sh[t] + sh[150 + t];
        size_t o = (size_t)b * KPU + t;
        split2(s, g_shi[o], g_slo[o]);
    }
}

// ---------------- internal-level combine + fused pair-sum -------------------------
__global__ __launch_bounds__(320)
void k_combine(int s, int cs, const int* __restrict__ xid,
               const float* __restrict__ biou, const float* __restrict__ bf)
{
    __shared__ float sh[300];
    const int t = threadIdx.x;
    const int b = blockIdx.x;
    if (t < 300) {
        int child = (t >= 150);
        int j = t - child * 150;
        int k = 2 * b + child;
        int p = s + k;
        const float* ew  = g_EW + (size_t)xid[p] * NPACK;
        const float* hio = g_hiou + (size_t)k * HS3;
        float iv = ew[j]          + hio[j]          + biou[j];
        float ov = ew[HS + j]     + hio[HS + j]     + biou[HS + j];
        float uv = ew[2 * HS + j] + hio[2 * HS + j] + biou[2 * HS + j];
        float xf = ew[HS3 + j] + bf[j];
        float fl = sig_f(xf + g_hUf[(size_t)(2 * k) * HS + j]);
        float fr = sig_f(xf + g_hUf[(size_t)(2 * k + 1) * HS + j]);
        float cl = g_c[(size_t)(cs + 2 * k) * HS + j];
        float cr = g_c[(size_t)(cs + 2 * k + 1) * HS + j];
        float cv = sig_f(iv) * tanh_f(uv) + fl * cl + fr * cr;
        float hv = sig_f(ov) * tanh_f(cv);
        g_c[(size_t)p * HS + j] = cv;
        size_t o = (size_t)p * KPU + j;
        split2(hv, g_hhi[o], g_hlo[o]);
        sh[t] = hv;
    }
    __syncthreads();
    if (t < 150) {
        float sum = sh[t] + sh[150 + t];
        size_t o = (size_t)b * KPU + t;
        split2(sum, g_shi[o], g_slo[o]);
    }
}

// ---------------- small levels: fused GEMV + gates (fp32 exact) -------------------
// one block per parent; levels with M <= 64.
__global__ __launch_bounds__(256)
void k_small(int s, int cs, const float* __restrict__ Uiou, const float* __restrict__ Uf,
             const int* __restrict__ xid, const float* __restrict__ biou,
             const float* __restrict__ bf)
{
    __shared__ float hl_[HS], hr_[HS], hs_[HS];
    __shared__ float io_[HS3], fl_[HS], fr_[HS];
    const int t = threadIdx.x;
    const int k = blockIdx.x;
    const int p = s + k;

    for (int j = t; j < HS; j += 256) {
        size_t cL = (size_t)(cs + 2 * k) * KPU + j;
        size_t cR = cL + KPU;
        float hl = __bfloat162float(g_hhi[cL]) + __bfloat162float(g_hlo[cL]);
        float hr = __bfloat162float(g_hhi[cR]) + __bfloat162float(g_hlo[cR]);
        hl_[j] = hl; hr_[j] = hr; hs_[j] = hl + hr;
    }
    __syncthreads();

    for (int j = t; j < HS3; j += 256) {
        float a = 0.0f;
        #pragma unroll 5
        for (int kk = 0; kk < HS; kk++) a = fmaf(hs_[kk], Uiou[kk * HS3 + j], a);
        io_[j] = a;
    }
    for (int j = t; j < HS; j += 256) {
        float al = 0.0f, ar = 0.0f;
        #pragma unroll 5
        for (int kk = 0; kk < HS; kk++) {
            float u = Uf[kk * HS + j];
            al = fmaf(hl_[kk], u, al);
            ar = fmaf(hr_[kk], u, ar);
        }
        fl_[j] = al; fr_[j] = ar;
    }
    __syncthreads();

    if (t < HS) {
        int j = t;
        const float* ew = g_EW + (size_t)xid[p] * NPACK;
        float iv = ew[j] + io_[j] + biou[j];
        float ov = ew[HS + j] + io_[HS + j] + biou[HS + j];
        float uv = ew[2 * HS + j] + io_[2 * HS + j] + biou[2 * HS + j];
        float xf = ew[HS3 + j] + bf[j];
        float fl = sig_f(xf + fl_[j]);
        float fr = sig_f(xf + fr_[j]);
        float cl = g_c[(size_t)(cs + 2 * k) * HS + j];
        float cr = g_c[(size_t)(cs + 2 * k + 1) * HS + j];
        float cv = sig_f(iv) * tanh_f(uv) + fl * cl + fr * cr;
        float hv = sig_f(ov) * tanh_f(cv);
        g_c[(size_t)p * HS + j] = cv;
        size_t o = (size_t)p * KPU + j;
        split2(hv, g_hhi[o], g_hlo[o]);
    }
}

// ---------------- output projection ----------------------------------------------
__global__ void k_out(const float* __restrict__ Wout, const float* __restrict__ bout,
                      float* __restrict__ out)
{
    __shared__ float sW[HS * NC];
    for (int i = threadIdx.x; i < HS * NC; i += blockDim.x) sW[i] = Wout[i];
    __syncthreads();
    int gw = (blockIdx.x * blockDim.x + threadIdx.x) >> 5;
    int lane = threadIdx.x & 31;
    if (gw >= NNODES) return;
    const __nv_bfloat16* hh = g_hhi + (size_t)gw * KPU;
    const __nv_bfloat16* hl = g_hlo + (size_t)gw * KPU;
    float a0 = 0.f, a1 = 0.f, a2 = 0.f, a3 = 0.f, a4 = 0.f;
    for (int j = lane; j < HS; j += 32) {
        float hv = __bfloat162float(hh[j]) + __bfloat162float(hl[j]);
        const float* w = sW + j * NC;
        a0 = fmaf(hv, w[0], a0);
        a1 = fmaf(hv, w[1], a1);
        a2 = fmaf(hv, w[2], a2);
        a3 = fmaf(hv, w[3], a3);
        a4 = fmaf(hv, w[4], a4);
    }
    #pragma unroll
    for (int off = 16; off; off >>= 1) {
        a0 += __shfl_xor_sync(0xffffffffu, a0, off);
        a1 += __shfl_xor_sync(0xffffffffu, a1, off);
        a2 += __shfl_xor_sync(0xffffffffu, a2, off);
        a3 += __shfl_xor_sync(0xffffffffu, a3, off);
        a4 += __shfl_xor_sync(0xffffffffu, a4, off);
    }
    if (lane == 0) {
        float* o = out + (size_t)gw * NC;
        o[0] = a0 + bout[0]; o[1] = a1 + bout[1]; o[2] = a2 + bout[2];
        o[3] = a3 + bout[3]; o[4] = a4 + bout[4];
    }
}

// ---------------- host orchestration ---------------------------------------------
extern "C" void kernel_launch(void* const* d_in, const int* in_sizes, int n_in,
                              void* d_out, int out_size)
{
    (void)in_sizes; (void)n_in; (void)out_size;
    const int*   xid  = (const int*)d_in[0];
    const float* emb  = (const float*)d_in[1];
    const float* Wiou = (const float*)d_in[2];
    const float* Uiou = (const float*)d_in[3];
    const float* biou = (const float*)d_in[4];
    const float* Wf   = (const float*)d_in[5];
    const float* Uf   = (const float*)d_in[6];
    const float* bf   = (const float*)d_in[7];
    const float* Wout = (const float*)d_in[8];
    const float* bout = (const float*)d_in[9];
    float* out = (float*)d_out;

    float *pEW, *pHiou, *pHUf;
    __nv_bfloat16 *pEhi, *pElo, *pBwh, *pBwl, *pBuh, *pBul, *pHhi, *pHlo, *pShi, *pSlo;
    cudaGetSymbolAddress((void**)&pEW,   g_EW);
    cudaGetSymbolAddress((void**)&pHiou, g_hiou);
    cudaGetSymbolAddress((void**)&pHUf,  g_hUf);
    cudaGetSymbolAddress((void**)&pEhi,  g_Ehi);
    cudaGetSymbolAddress((void**)&pElo,  g_Elo);
    cudaGetSymbolAddress((void**)&pBwh,  g_Bwh);
    cudaGetSymbolAddress((void**)&pBwl,  g_Bwl);
    cudaGetSymbolAddress((void**)&pBuh,  g_Buh);
    cudaGetSymbolAddress((void**)&pBul,  g_Bul);
    cudaGetSymbolAddress((void**)&pHhi,  g_hhi);
    cudaGetSymbolAddress((void**)&pHlo,  g_hlo);
    cudaGetSymbolAddress((void**)&pShi,  g_shi);
    cudaGetSymbolAddress((void**)&pSlo,  g_slo);

    cudaFuncSetAttribute(k_mma, cudaFuncAttributeMaxDynamicSharedMemorySize, SMEMT);

    const dim3 thr(256);
    k_prep_w<<<(NBROW * KPW + NBROW * KPU + 255) / 256, thr>>>(Wiou, Wf, Uiou, Uf);
    k_prep_emb<<<(VPAD * KPW + 255) / 256, thr>>>(emb);
    {
        int zt = (NNODES + 128) * 10 + (LEAVES / 2) * 10;
        k_zeropads<<<(zt + 255) / 256, thr>>>();
    }

    // Vocab precompute: g_EW = emb @ [W_iou | W_f]
    k_mma<<<dim3(5, VPAD / 128), thr, SMEMT>>>(pEhi, pElo, VOCAB, KPW, pBwh, pBwl,
                                               NPACK, pEW, NPACK);

    // Leaf level: gates + psum for level 17.
    k_leaf<<<LEAVES / 2, 320>>>(xid, biou);

    // Levels 17..7: GEMM path (psum produced by previous stage).
    for (int lvl = DEPTH - 1; lvl >= LVL_SMALL; lvl--) {
        int M  = 1 << lvl;
        int s  = M - 1;
        int cs = 2 * M - 1;
        k_mma<<<dim3(4, (M + 127) / 128), thr, SMEMT>>>(
            pShi, pSlo, M, KPU, pBuh, pBul, HS3, pHiou, HS3);
        k_mma<<<dim3(2, (2 * M + 127) / 128), thr, SMEMT>>>(
            pHhi + (size_t)cs * KPU, pHlo + (size_t)cs * KPU, 2 * M, KPU,
            pBuh + (size_t)HS3 * KPU, pBul + (size_t)HS3 * KPU, HS, pHUf, HS);
        k_combine<<<M / 2, 320>>>(s, cs, xid, biou, bf);
    }

    // Levels 6..0: fused GEMV path.
    for (int lvl = LVL_SMALL - 1; lvl >= 0; lvl--) {
        int M  = 1 << lvl;
        int s  = M - 1;
        int cs = 2 * M - 1;
        k_small<<<M, 256>>>(s, cs, Uiou, Uf, xid, biou, bf);
    }

    k_out<<<(NNODES + 7) / 8, thr>>>(Wout, bout, out);
}

// round 6
// speedup vs baseline: 2.1504x; 1.0628x over previous
#include <cuda_runtime.h>
#include <cuda_bf16.h>
#include <cstdint>
#include <cstddef>

#define VOCAB   50000
#define VPAD    50048        // 391 * 128
#define XS      300
#define HS      150
#define HS3     450
#define NPACK   600          // [iou(450) | f(150)]
#define NBROW   768
#define NC      5
#define DEPTH   18
#define NNODES  524287
#define LEAVES  262144
#define KPW     320
#define KPU     160
#define LVL_SMALL 7

// ---------------- static device scratch ------------------------------------------
__device__ float g_EW[(size_t)VOCAB * NPACK];
__device__ float g_hiou[(size_t)(LEAVES / 2) * HS3];
__device__ float g_hUf[(size_t)LEAVES * HS];
__device__ float g_c[(size_t)NNODES * HS];
__device__ __nv_bfloat16 g_hhi[(size_t)(NNODES + 128) * KPU];
__device__ __nv_bfloat16 g_hlo[(size_t)(NNODES + 128) * KPU];
__device__ __nv_bfloat16 g_shi[(size_t)(LEAVES / 2) * KPU];
__device__ __nv_bfloat16 g_slo[(size_t)(LEAVES / 2) * KPU];
__device__ __nv_bfloat16 g_Ehi[(size_t)VPAD * KPW];
__device__ __nv_bfloat16 g_Elo[(size_t)VPAD * KPW];
__device__ __nv_bfloat16 g_Bwh[(size_t)NBROW * KPW];
__device__ __nv_bfloat16 g_Bwl[(size_t)NBROW * KPW];
__device__ __nv_bfloat16 g_Buh[(size_t)NBROW * KPU];
__device__ __nv_bfloat16 g_Bul[(size_t)NBROW * KPU];

// ---------------- helpers ---------------------------------------------------------
__device__ __forceinline__ uint32_t smem_u32(const void* p) {
    uint32_t a;
    asm("{ .reg .u64 t; cvta.to.shared.u64 t, %1; cvt.u32.u64 %0, t; }" : "=r"(a) : "l"(p));
    return a;
}
__device__ __forceinline__ void split2(float v, __nv_bfloat16& h, __nv_bfloat16& l) {
    h = __float2bfloat16_rn(v);
    l = __float2bfloat16_rn(v - __bfloat162float(h));
}
#define CP16(dst, src) \
    asm volatile("cp.async.cg.shared.global [%0], [%1], 16;" :: "r"(dst), "l"(src))
#define CP_COMMIT() asm volatile("cp.async.commit_group;" ::: "memory")
#define CP_WAIT1()  asm volatile("cp.async.wait_group 1;" ::: "memory")
#define CP_WAIT0()  asm volatile("cp.async.wait_group 0;" ::: "memory")
#define LDSM4(r0, r1, r2, r3, addr)                                               \
    asm volatile("ldmatrix.sync.aligned.m8n8.x4.shared.b16 {%0,%1,%2,%3}, [%4];"  \
                 : "=r"(r0), "=r"(r1), "=r"(r2), "=r"(r3) : "r"(addr))

// ---------------- FMA-only activations -------------------------------------------
__device__ __forceinline__ float sig_f(float x) {
    float ax = fabsf(x);
    if (ax > 1.0f) return 1.0f / (1.0f + __expf(-x));
    float x2 = x * x;
    float p = fmaf(x2, 2.1357958e-5f, -2.1081349e-4f);
    p = fmaf(x2, p, 2.0833333e-3f);
    p = fmaf(x2, p, -2.0833333e-2f);
    p = fmaf(x2, p, 0.25f);
    return fmaf(x, p, 0.5f);
}
__device__ __forceinline__ float tanh_f(float x) {
    float ax = fabsf(x);
    if (ax > 0.55f) {
        float t = __expf(-2.0f * ax);
        float r = __fdividef(1.0f - t, 1.0f + t);
        return x < 0.0f ? -r : r;
    }
    float x2 = x * x;
    float p = fmaf(x2, 2.1869488e-2f, -5.3968254e-2f);
    p = fmaf(x2, p, 1.3333333e-1f);
    p = fmaf(x2, p, -3.3333333e-1f);
    p = fmaf(x2, p, 1.0f);
    return x * p;
}

// ---------------- prep kernels ----------------------------------------------------
__global__ void k_prep_w(const float* __restrict__ Wiou, const float* __restrict__ Wf,
                         const float* __restrict__ Uiou, const float* __restrict__ Uf)
{
    int idx = blockIdx.x * blockDim.x + threadIdx.x;
    const int NW = NBROW * KPW;
    const int NU = NBROW * KPU;
    if (idx < NW) {
        int n = idx / KPW, k = idx - n * KPW;
        float v = 0.0f;
        if (k < XS && n < NPACK) v = (n < HS3) ? Wiou[k * HS3 + n] : Wf[k * HS + (n - HS3)];
        split2(v, g_Bwh[idx], g_Bwl[idx]);
    } else if (idx < NW + NU) {
        int j = idx - NW;
        int n = j / KPU, k = j - n * KPU;
        float v = 0.0f;
        if (k < HS && n < NPACK) v = (n < HS3) ? Uiou[k * HS3 + n] : Uf[k * HS + (n - HS3)];
        split2(v, g_Buh[j], g_Bul[j]);
    }
}

__global__ void k_prep_emb(const float* __restrict__ emb)
{
    int idx = blockIdx.x * blockDim.x + threadIdx.x;
    if (idx >= VPAD * KPW) return;
    int r = idx / KPW, k = idx - r * KPW;
    float v = (r < VOCAB && k < XS) ? emb[(size_t)r * XS + k] : 0.0f;
    split2(v, g_Ehi[idx], g_Elo[idx]);
}

__global__ void k_zeropads()
{
    int idx = blockIdx.x * blockDim.x + threadIdx.x;
    const int T1 = (NNODES + 128) * 10;
    const int T2 = (LEAVES / 2) * 10;
    if (idx < T1) {
        int r = idx / 10, k = HS + idx % 10;
        g_hhi[(size_t)r * KPU + k] = __nv_bfloat16(0.0f);
        g_hlo[(size_t)r * KPU + k] = __nv_bfloat16(0.0f);
    } else if (idx < T1 + T2) {
        int j = idx - T1;
        int r = j / 10, k = HS + j % 10;
        g_shi[(size_t)r * KPU + k] = __nv_bfloat16(0.0f);
        g_slo[(size_t)r * KPU + k] = __nv_bfloat16(0.0f);
    }
}

// ---------------- cp.async + ldmatrix bf16x3-split mma.sync GEMM ------------------
#define MMA_BF16(d, a0, a1, a2, a3, b0, b1)                                      \
    asm volatile("mma.sync.aligned.m16n8k16.row.col.f32.bf16.bf16.f32 "          \
                 "{%0,%1,%2,%3},{%4,%5,%6,%7},{%8,%9},{%0,%1,%2,%3};"            \
                 : "+f"(d[0]), "+f"(d[1]), "+f"(d[2]), "+f"(d[3])                \
                 : "r"(a0), "r"(a1), "r"(a2), "r"(a3), "r"(b0), "r"(b1))

#define SROW   20                     // u32 per smem row (64B data + 16B pad)
#define PLANEB 10240                  // 128 rows * 80B
#define STAGEB 40960                  // 4 planes
#define SMEMT  81920                  // 2 stages

__global__ __launch_bounds__(256, 2)
void k_mma(const __nv_bfloat16* __restrict__ Ahi, const __nv_bfloat16* __restrict__ Alo,
           int M, int Kpad,
           const __nv_bfloat16* __restrict__ Bhi, const __nv_bfloat16* __restrict__ Blo,
           int Nact, float* __restrict__ C, int ldc)
{
    extern __shared__ char smem[];
    const uint32_t sb = smem_u32(smem);
    const int tid  = threadIdx.x;
    const int lane = tid & 31;
    const int wid  = tid >> 5;
    const int row0 = blockIdx.y << 7;
    const int col0 = blockIdx.x << 7;
    const int m0 = (wid & 3) << 5;
    const int n0 = (wid >> 2) << 6;
    const int g   = lane >> 2;
    const int tig = lane & 3;

    // per-thread ldmatrix address components (bytes within plane)
    const int lr   = lane & 7;
    const uint32_t aOff = (uint32_t)(m0 + lr + (((lane >> 3) & 1) << 3)) * 80
                        + (uint32_t)((lane >> 4) << 4);
    const uint32_t bOff = (uint32_t)(n0 + lr + ((lane >> 4) << 3)) * 80
                        + (uint32_t)(((lane >> 3) & 1) << 4);

    const char* pA_h = (const char*)(Ahi + (size_t)row0 * Kpad);
    const char* pA_l = (const char*)(Alo + (size_t)row0 * Kpad);
    const char* pB_h = (const char*)(Bhi + (size_t)col0 * Kpad);
    const char* pB_l = (const char*)(Blo + (size_t)col0 * Kpad);

    const int r_ld  = tid >> 1;
    const int sg2   = (tid & 1) << 1;

    float d[2][8][4];
    #pragma unroll
    for (int mb = 0; mb < 2; mb++)
        #pragma unroll
        for (int nb = 0; nb < 8; nb++)
            #pragma unroll
            for (int q = 0; q < 4; q++) d[mb][nb][q] = 0.0f;

    auto load_chunk = [&](int kb, int st) {
        uint32_t dbase = sb + st * STAGEB + r_ld * 80 + sg2 * 16;
        size_t   soff  = ((size_t)r_ld * Kpad + kb + sg2 * 8) * 2;
        CP16(dbase,               pA_h + soff);
        CP16(dbase + 16,          pA_h + soff + 16);
        CP16(dbase + PLANEB,      pA_l + soff);
        CP16(dbase + PLANEB + 16, pA_l + soff + 16);
        CP16(dbase + 2 * PLANEB,      pB_h + soff);
        CP16(dbase + 2 * PLANEB + 16, pB_h + soff + 16);
        CP16(dbase + 3 * PLANEB,      pB_l + soff);
        CP16(dbase + 3 * PLANEB + 16, pB_l + soff + 16);
    };

    const int chunks = Kpad >> 5;
    load_chunk(0, 0);
    CP_COMMIT();

    for (int c = 0; c < chunks; c++) {
        if (c + 1 < chunks) {
            load_chunk((c + 1) << 5, (c + 1) & 1);
            CP_COMMIT();
            CP_WAIT1();
        } else {
            CP_WAIT0();
        }
        __syncthreads();

        const uint32_t sbase = sb + (c & 1) * STAGEB;

        #pragma unroll
        for (int ks = 0; ks < 2; ks++) {
            uint32_t ah[2][4], al[2][4];
            #pragma unroll
            for (int mb = 0; mb < 2; mb++) {
                uint32_t aoff = sbase + aOff + mb * (16 * 80) + ks * 32;
                LDSM4(ah[mb][0], ah[mb][1], ah[mb][2], ah[mb][3], aoff);
                LDSM4(al[mb][0], al[mb][1], al[mb][2], al[mb][3], aoff + PLANEB);
            }
            #pragma unroll
            for (int pr = 0; pr < 4; pr++) {
                uint32_t boff = sbase + 2 * PLANEB + bOff + pr * (16 * 80) + ks * 32;
                uint32_t bh[4], bl[4];
                LDSM4(bh[0], bh[1], bh[2], bh[3], boff);
                LDSM4(bl[0], bl[1], bl[2], bl[3], boff + PLANEB);
                #pragma unroll
                for (int mb = 0; mb < 2; mb++) {
                    MMA_BF16(d[mb][2 * pr],     ah[mb][0], ah[mb][1], ah[mb][2], ah[mb][3], bh[0], bh[1]);
                    MMA_BF16(d[mb][2 * pr + 1], ah[mb][0], ah[mb][1], ah[mb][2], ah[mb][3], bh[2], bh[3]);
                    MMA_BF16(d[mb][2 * pr],     ah[mb][0], ah[mb][1], ah[mb][2], ah[mb][3], bl[0], bl[1]);
                    MMA_BF16(d[mb][2 * pr + 1], ah[mb][0], ah[mb][1], ah[mb][2], ah[mb][3], bl[2], bl[3]);
                    MMA_BF16(d[mb][2 * pr],     al[mb][0], al[mb][1], al[mb][2], al[mb][3], bh[0], bh[1]);
                    MMA_BF16(d[mb][2 * pr + 1], al[mb][0], al[mb][1], al[mb][2], al[mb][3], bh[2], bh[3]);
                }
            }
        }
        __syncthreads();
    }

    #pragma unroll
    for (int mb = 0; mb < 2; mb++) {
        int gr = row0 + m0 + mb * 16 + g;
        #pragma unroll
        for (int nb = 0; nb < 8; nb++) {
            int gc = col0 + n0 + nb * 8 + tig * 2;
            if (gc < Nact) {
                if (gr < M)
                    *(float2*)(C + (size_t)gr * ldc + gc) = make_float2(d[mb][nb][0], d[mb][nb][1]);
                if (gr + 8 < M)
                    *(float2*)(C + (size_t)(gr + 8) * ldc + gc) = make_float2(d[mb][nb][2], d[mb][nb][3]);
            }
        }
    }
}

// ---------------- leaf level: gates + fused pair-sum + fused out ------------------
__global__ __launch_bounds__(320)
void k_leaf(const int* __restrict__ xid, const float* __restrict__ biou,
            const float* __restrict__ Wout, const float* __restrict__ bout,
            float* __restrict__ out)
{
    __shared__ float sh[300];
    const int t = threadIdx.x;
    const int b = blockIdx.x;
    if (t < 300) {
        int child = (t >= 150);
        int j = t - child * 150;
        int i = 2 * b + child;
        int n = (LEAVES - 1) + i;
        const float* ew = g_EW + (size_t)xid[n] * NPACK;
        float iv = ew[j] + biou[j];
        float ov = ew[HS + j] + biou[HS + j];
        float uv = ew[2 * HS + j] + biou[2 * HS + j];
        float cv = sig_f(iv) * tanh_f(uv);
        float hv = sig_f(ov) * tanh_f(cv);
        g_c[(size_t)n * HS + j] = cv;
        size_t o = (size_t)n * KPU + j;
        split2(hv, g_hhi[o], g_hlo[o]);
        sh[t] = hv;
    }
    __syncthreads();
    if (t < 150) {
        float s = sh[t] + sh[150 + t];
        size_t o = (size_t)b * KPU + t;
        split2(s, g_shi[o], g_slo[o]);
    }
    // fused output projection: warps 0..9 -> (node 0/1, class 0..4)
    int w = t >> 5, lane = t & 31;
    if (w < 10) {
        int nd = w / 5, q = w - nd * 5;
        float a = 0.f;
        for (int j = lane; j < HS; j += 32)
            a = fmaf(sh[nd * HS + j], Wout[j * NC + q], a);
        #pragma unroll
        for (int off = 16; off; off >>= 1) a += __shfl_xor_sync(0xffffffffu, a, off);
        if (lane == 0) {
            int n = (LEAVES - 1) + 2 * b + nd;
            out[(size_t)n * NC + q] = a + bout[q];
        }
    }
}

// ---------------- internal-level combine + fused pair-sum + fused out -------------
__global__ __launch_bounds__(320)
void k_combine(int s, int cs, const int* __restrict__ xid,
               const float* __restrict__ biou, const float* __restrict__ bf,
               const float* __restrict__ Wout, const float* __restrict__ bout,
               float* __restrict__ out)
{
    __shared__ float sh[300];
    const int t = threadIdx.x;
    const int b = blockIdx.x;
    if (t < 300) {
        int child = (t >= 150);
        int j = t - child * 150;
        int k = 2 * b + child;
        int p = s + k;
        const float* ew  = g_EW + (size_t)xid[p] * NPACK;
        const float* hio = g_hiou + (size_t)k * HS3;
        float iv = ew[j]          + hio[j]          + biou[j];
        float ov = ew[HS + j]     + hio[HS + j]     + biou[HS + j];
        float uv = ew[2 * HS + j] + hio[2 * HS + j] + biou[2 * HS + j];
        float xf = ew[HS3 + j] + bf[j];
        float fl = sig_f(xf + g_hUf[(size_t)(2 * k) * HS + j]);
        float fr = sig_f(xf + g_hUf[(size_t)(2 * k + 1) * HS + j]);
        float cl = g_c[(size_t)(cs + 2 * k) * HS + j];
        float cr = g_c[(size_t)(cs + 2 * k + 1) * HS + j];
        float cv = sig_f(iv) * tanh_f(uv) + fl * cl + fr * cr;
        float hv = sig_f(ov) * tanh_f(cv);
        g_c[(size_t)p * HS + j] = cv;
        size_t o = (size_t)p * KPU + j;
        split2(hv, g_hhi[o], g_hlo[o]);
        sh[t] = hv;
    }
    __syncthreads();
    if (t < 150) {
        float sum = sh[t] + sh[150 + t];
        size_t o = (size_t)b * KPU + t;
        split2(sum, g_shi[o], g_slo[o]);
    }
    int w = t >> 5, lane = t & 31;
    if (w < 10) {
        int nd = w / 5, q = w - nd * 5;
        float a = 0.f;
        for (int j = lane; j < HS; j += 32)
            a = fmaf(sh[nd * HS + j], Wout[j * NC + q], a);
        #pragma unroll
        for (int off = 16; off; off >>= 1) a += __shfl_xor_sync(0xffffffffu, a, off);
        if (lane == 0) {
            int p = s + 2 * b + nd;
            out[(size_t)p * NC + q] = a + bout[q];
        }
    }
}

// ---------------- small levels: fused GEMV + gates + out (fp32 exact) -------------
__global__ __launch_bounds__(256)
void k_small(int s, int cs, const float* __restrict__ Uiou, const float* __restrict__ Uf,
             const int* __restrict__ xid, const float* __restrict__ biou,
             const float* __restrict__ bf,
             const float* __restrict__ Wout, const float* __restrict__ bout,
             float* __restrict__ out)
{
    __shared__ float hl_[HS], hr_[HS], hs_[HS], ho_[HS];
    __shared__ float io_[HS3], fl_[HS], fr_[HS];
    const int t = threadIdx.x;
    const int k = blockIdx.x;
    const int p = s + k;

    for (int j = t; j < HS; j += 256) {
        size_t cL = (size_t)(cs + 2 * k) * KPU + j;
        size_t cR = cL + KPU;
        float hl = __bfloat162float(g_hhi[cL]) + __bfloat162float(g_hlo[cL]);
        float hr = __bfloat162float(g_hhi[cR]) + __bfloat162float(g_hlo[cR]);
        hl_[j] = hl; hr_[j] = hr; hs_[j] = hl + hr;
    }
    __syncthreads();

    for (int j = t; j < HS3; j += 256) {
        float a = 0.0f;
        #pragma unroll 5
        for (int kk = 0; kk < HS; kk++) a = fmaf(hs_[kk], Uiou[kk * HS3 + j], a);
        io_[j] = a;
    }
    for (int j = t; j < HS; j += 256) {
        float al = 0.0f, ar = 0.0f;
        #pragma unroll 5
        for (int kk = 0; kk < HS; kk++) {
            float u = Uf[kk * HS + j];
            al = fmaf(hl_[kk], u, al);
            ar = fmaf(hr_[kk], u, ar);
        }
        fl_[j] = al; fr_[j] = ar;
    }
    __syncthreads();

    if (t < HS) {
        int j = t;
        const float* ew = g_EW + (size_t)xid[p] * NPACK;
        float iv = ew[j] + io_[j] + biou[j];
        float ov = ew[HS + j] + io_[HS + j] + biou[HS + j];
        float uv = ew[2 * HS + j] + io_[2 * HS + j] + biou[2 * HS + j];
        float xf = ew[HS3 + j] + bf[j];
        float fl = sig_f(xf + fl_[j]);
        float fr = sig_f(xf + fr_[j]);
        float cl = g_c[(size_t)(cs + 2 * k) * HS + j];
        float cr = g_c[(size_t)(cs + 2 * k + 1) * HS + j];
        float cv = sig_f(iv) * tanh_f(uv) + fl * cl + fr * cr;
        float hv = sig_f(ov) * tanh_f(cv);
        g_c[(size_t)p * HS + j] = cv;
        size_t o = (size_t)p * KPU + j;
        split2(hv, g_hhi[o], g_hlo[o]);
        ho_[j] = hv;
    }
    __syncthreads();
    int w = t >> 5, lane = t & 31;
    if (w < NC) {
        float a = 0.f;
        for (int j = lane; j < HS; j += 32)
            a = fmaf(ho_[j], Wout[j * NC + w], a);
        #pragma unroll
        for (int off = 16; off; off >>= 1) a += __shfl_xor_sync(0xffffffffu, a, off);
        if (lane == 0) out[(size_t)p * NC + w] = a + bout[w];
    }
}

// ---------------- host orchestration ---------------------------------------------
extern "C" void kernel_launch(void* const* d_in, const int* in_sizes, int n_in,
                              void* d_out, int out_size)
{
    (void)in_sizes; (void)n_in; (void)out_size;
    const int*   xid  = (const int*)d_in[0];
    const float* emb  = (const float*)d_in[1];
    const float* Wiou = (const float*)d_in[2];
    const float* Uiou = (const float*)d_in[3];
    const float* biou = (const float*)d_in[4];
    const float* Wf   = (const float*)d_in[5];
    const float* Uf   = (const float*)d_in[6];
    const float* bf   = (const float*)d_in[7];
    const float* Wout = (const float*)d_in[8];
    const float* bout = (const float*)d_in[9];
    float* out = (float*)d_out;

    float *pEW, *pHiou, *pHUf;
    __nv_bfloat16 *pEhi, *pElo, *pBwh, *pBwl, *pBuh, *pBul, *pHhi, *pHlo, *pShi, *pSlo;
    cudaGetSymbolAddress((void**)&pEW,   g_EW);
    cudaGetSymbolAddress((void**)&pHiou, g_hiou);
    cudaGetSymbolAddress((void**)&pHUf,  g_hUf);
    cudaGetSymbolAddress((void**)&pEhi,  g_Ehi);
    cudaGetSymbolAddress((void**)&pElo,  g_Elo);
    cudaGetSymbolAddress((void**)&pBwh,  g_Bwh);
    cudaGetSymbolAddress((void**)&pBwl,  g_Bwl);
    cudaGetSymbolAddress((void**)&pBuh,  g_Buh);
    cudaGetSymbolAddress((void**)&pBul,  g_Bul);
    cudaGetSymbolAddress((void**)&pHhi,  g_hhi);
    cudaGetSymbolAddress((void**)&pHlo,  g_hlo);
    cudaGetSymbolAddress((void**)&pShi,  g_shi);
    cudaGetSymbolAddress((void**)&pSlo,  g_slo);

    cudaFuncSetAttribute(k_mma, cudaFuncAttributeMaxDynamicSharedMemorySize, SMEMT);

    const dim3 thr(256);
    k_prep_w<<<(NBROW * KPW + NBROW * KPU + 255) / 256, thr>>>(Wiou, Wf, Uiou, Uf);
    k_prep_emb<<<(VPAD * KPW + 255) / 256, thr>>>(emb);
    {
        int zt = (NNODES + 128) * 10 + (LEAVES / 2) * 10;
        k_zeropads<<<(zt + 255) / 256, thr>>>();
    }

    // Vocab precompute: g_EW = emb @ [W_iou | W_f]
    k_mma<<<dim3(5, VPAD / 128), thr, SMEMT>>>(pEhi, pElo, VOCAB, KPW, pBwh, pBwl,
                                               NPACK, pEW, NPACK);

    // Leaf level: gates + psum + out.
    k_leaf<<<LEAVES / 2, 320>>>(xid, biou, Wout, bout, out);

    // Levels 17..7: GEMM path.
    for (int lvl = DEPTH - 1; lvl >= LVL_SMALL; lvl--) {
        int M  = 1 << lvl;
        int s  = M - 1;
        int cs = 2 * M - 1;
        k_mma<<<dim3(4, (M + 127) / 128), thr, SMEMT>>>(
            pShi, pSlo, M, KPU, pBuh, pBul, HS3, pHiou, HS3);
        k_mma<<<dim3(2, (2 * M + 127) / 128), thr, SMEMT>>>(
            pHhi + (size_t)cs * KPU, pHlo + (size_t)cs * KPU, 2 * M, KPU,
            pBuh + (size_t)HS3 * KPU, pBul + (size_t)HS3 * KPU, HS, pHUf, HS);
        k_combine<<<M / 2, 320>>>(s, cs, xid, biou, bf, Wout, bout, out);
    }

    // Levels 6..0: fused GEMV path.
    for (int lvl = LVL_SMALL - 1; lvl >= 0; lvl--) {
        int M  = 1 << lvl;
        int s  = M - 1;
        int cs = 2 * M - 1;
        k_small<<<M, 256>>>(s, cs, Uiou, Uf, xid, biou, bf, Wout, bout, out);
    }
}

// round 7
// speedup vs baseline: 3.0516x; 1.4191x over previous
#include <cuda_runtime.h>
#include <cuda_fp16.h>
#include <cstdint>
#include <cstddef>

#define VOCAB   50000
#define VPAD    50048        // 391 * 128
#define XS      300
#define HS      150
#define HS3     450
#define NPACK   600          // [iou(450) | f(150)]
#define NBROW   768
#define NC      5
#define DEPTH   18
#define NNODES  524287
#define LEAVES  262144
#define KPW     320
#define KPU     160
#define LVL_SMALL 7

// ---------------- static device scratch ------------------------------------------
__device__ float g_EW[(size_t)VOCAB * NPACK];
__device__ float g_hiou[(size_t)(LEAVES / 2) * HS3];
__device__ float g_hUf[(size_t)LEAVES * HS];
__device__ float g_c[(size_t)NNODES * HS];
__device__ __half g_hf[(size_t)(NNODES + 128) * KPU];     // h, fp16
__device__ __half g_sf[(size_t)(LEAVES / 2) * KPU];       // pair-sum h, fp16
__device__ __half g_Ef[(size_t)VPAD * KPW];               // emb, fp16
__device__ __half g_Bw[(size_t)NBROW * KPW];              // [W_iou|W_f]^T fp16
__device__ __half g_Bu[(size_t)NBROW * KPU];              // [U_iou|U_f]^T fp16

// ---------------- helpers ---------------------------------------------------------
__device__ __forceinline__ uint32_t smem_u32(const void* p) {
    uint32_t a;
    asm("{ .reg .u64 t; cvta.to.shared.u64 t, %1; cvt.u32.u64 %0, t; }" : "=r"(a) : "l"(p));
    return a;
}
#define CP16(dst, src) \
    asm volatile("cp.async.cg.shared.global [%0], [%1], 16;" :: "r"(dst), "l"(src))
#define CP_COMMIT() asm volatile("cp.async.commit_group;" ::: "memory")
#define CP_WAIT1()  asm volatile("cp.async.wait_group 1;" ::: "memory")
#define CP_WAIT0()  asm volatile("cp.async.wait_group 0;" ::: "memory")
#define LDSM4(r0, r1, r2, r3, addr)                                               \
    asm volatile("ldmatrix.sync.aligned.m8n8.x4.shared.b16 {%0,%1,%2,%3}, [%4];"  \
                 : "=r"(r0), "=r"(r1), "=r"(r2), "=r"(r3) : "r"(addr))
#define MMA_F16(d, a0, a1, a2, a3, b0, b1)                                       \
    asm volatile("mma.sync.aligned.m16n8k16.row.col.f32.f16.f16.f32 "            \
                 "{%0,%1,%2,%3},{%4,%5,%6,%7},{%8,%9},{%0,%1,%2,%3};"            \
                 : "+f"(d[0]), "+f"(d[1]), "+f"(d[2]), "+f"(d[3])                \
                 : "r"(a0), "r"(a1), "r"(a2), "r"(a3), "r"(b0), "r"(b1))

// ---------------- FMA-only activations -------------------------------------------
__device__ __forceinline__ float sig_f(float x) {
    float ax = fabsf(x);
    if (ax > 1.0f) return 1.0f / (1.0f + __expf(-x));
    float x2 = x * x;
    float p = fmaf(x2, 2.1357958e-5f, -2.1081349e-4f);
    p = fmaf(x2, p, 2.0833333e-3f);
    p = fmaf(x2, p, -2.0833333e-2f);
    p = fmaf(x2, p, 0.25f);
    return fmaf(x, p, 0.5f);
}
__device__ __forceinline__ float tanh_f(float x) {
    float ax = fabsf(x);
    if (ax > 0.55f) {
        float t = __expf(-2.0f * ax);
        float r = __fdividef(1.0f - t, 1.0f + t);
        return x < 0.0f ? -r : r;
    }
    float x2 = x * x;
    float p = fmaf(x2, 2.1869488e-2f, -5.3968254e-2f);
    p = fmaf(x2, p, 1.3333333e-1f);
    p = fmaf(x2, p, -3.3333333e-1f);
    p = fmaf(x2, p, 1.0f);
    return x * p;
}

// ---------------- prep kernels ----------------------------------------------------
__global__ void k_prep_w(const float* __restrict__ Wiou, const float* __restrict__ Wf,
                         const float* __restrict__ Uiou, const float* __restrict__ Uf)
{
    int idx = blockIdx.x * blockDim.x + threadIdx.x;
    const int NW = NBROW * KPW;
    const int NU = NBROW * KPU;
    if (idx < NW) {
        int n = idx / KPW, k = idx - n * KPW;
        float v = 0.0f;
        if (k < XS && n < NPACK) v = (n < HS3) ? Wiou[k * HS3 + n] : Wf[k * HS + (n - HS3)];
        g_Bw[idx] = __float2half_rn(v);
    } else if (idx < NW + NU) {
        int j = idx - NW;
        int n = j / KPU, k = j - n * KPU;
        float v = 0.0f;
        if (k < HS && n < NPACK) v = (n < HS3) ? Uiou[k * HS3 + n] : Uf[k * HS + (n - HS3)];
        g_Bu[j] = __float2half_rn(v);
    }
}

__global__ void k_prep_emb(const float* __restrict__ emb)
{
    int idx = blockIdx.x * blockDim.x + threadIdx.x;
    if (idx >= VPAD * KPW) return;
    int r = idx / KPW, k = idx - r * KPW;
    float v = (r < VOCAB && k < XS) ? emb[(size_t)r * XS + k] : 0.0f;
    g_Ef[idx] = __float2half_rn(v);
}

__global__ void k_zeropads()
{
    int idx = blockIdx.x * blockDim.x + threadIdx.x;
    const int T1 = (NNODES + 128) * 10;
    const int T2 = (LEAVES / 2) * 10;
    if (idx < T1) {
        int r = idx / 10, k = HS + idx % 10;
        g_hf[(size_t)r * KPU + k] = __float2half_rn(0.0f);
    } else if (idx < T1 + T2) {
        int j = idx - T1;
        int r = j / 10, k = HS + j % 10;
        g_sf[(size_t)r * KPU + k] = __float2half_rn(0.0f);
    }
}

// ---------------- cp.async + ldmatrix fp16 mma.sync GEMM core ---------------------
#define SROW   20                     // u32 per smem row (64B data + 16B pad)
#define PLANEB 10240                  // 128 rows * 80B
#define STAGEB 20480                  // 2 planes (A, B)
#define SMEMT  40960                  // 2 stages

__device__ __forceinline__ void gemm_core(
    int bx, int by, char* smem,
    const __half* __restrict__ A, int M, int Kpad,
    const __half* __restrict__ B, int Nact, float* __restrict__ C, int ldc)
{
    const uint32_t sb = smem_u32(smem);
    const int tid  = threadIdx.x;
    const int lane = tid & 31;
    const int wid  = tid >> 5;
    const int row0 = by << 7;
    const int col0 = bx << 7;
    const int m0 = (wid & 3) << 5;
    const int n0 = (wid >> 2) << 6;
    const int g   = lane >> 2;
    const int tig = lane & 3;

    const int lr   = lane & 7;
    const uint32_t aOff = (uint32_t)(m0 + lr + (((lane >> 3) & 1) << 3)) * 80
                        + (uint32_t)((lane >> 4) << 4);
    const uint32_t bOff = (uint32_t)(n0 + lr + ((lane >> 4) << 3)) * 80
                        + (uint32_t)(((lane >> 3) & 1) << 4);

    const char* pA = (const char*)(A + (size_t)row0 * Kpad);
    const char* pB = (const char*)(B + (size_t)col0 * Kpad);

    const int r_ld = tid >> 1;
    const int sg2  = (tid & 1) << 1;

    float d[2][8][4];
    #pragma unroll
    for (int mb = 0; mb < 2; mb++)
        #pragma unroll
        for (int nb = 0; nb < 8; nb++)
            #pragma unroll
            for (int q = 0; q < 4; q++) d[mb][nb][q] = 0.0f;

    auto load_chunk = [&](int kb, int st) {
        uint32_t dbase = sb + st * STAGEB + r_ld * 80 + sg2 * 16;
        size_t   soff  = ((size_t)r_ld * Kpad + kb + sg2 * 8) * 2;
        CP16(dbase,               pA + soff);
        CP16(dbase + 16,          pA + soff + 16);
        CP16(dbase + PLANEB,      pB + soff);
        CP16(dbase + PLANEB + 16, pB + soff + 16);
    };

    const int chunks = Kpad >> 5;
    load_chunk(0, 0);
    CP_COMMIT();

    for (int c = 0; c < chunks; c++) {
        if (c + 1 < chunks) {
            load_chunk((c + 1) << 5, (c + 1) & 1);
            CP_COMMIT();
            CP_WAIT1();
        } else {
            CP_WAIT0();
        }
        __syncthreads();

        const uint32_t sbase = sb + (c & 1) * STAGEB;

        #pragma unroll
        for (int ks = 0; ks < 2; ks++) {
            uint32_t ah[2][4];
            #pragma unroll
            for (int mb = 0; mb < 2; mb++) {
                uint32_t aoff = sbase + aOff + mb * (16 * 80) + ks * 32;
                LDSM4(ah[mb][0], ah[mb][1], ah[mb][2], ah[mb][3], aoff);
            }
            #pragma unroll
            for (int pr = 0; pr < 4; pr++) {
                uint32_t boff = sbase + PLANEB + bOff + pr * (16 * 80) + ks * 32;
                uint32_t bh[4];
                LDSM4(bh[0], bh[1], bh[2], bh[3], boff);
                #pragma unroll
                for (int mb = 0; mb < 2; mb++) {
                    MMA_F16(d[mb][2 * pr],     ah[mb][0], ah[mb][1], ah[mb][2], ah[mb][3], bh[0], bh[1]);
                    MMA_F16(d[mb][2 * pr + 1], ah[mb][0], ah[mb][1], ah[mb][2], ah[mb][3], bh[2], bh[3]);
                }
            }
        }
        __syncthreads();
    }

    #pragma unroll
    for (int mb = 0; mb < 2; mb++) {
        int gr = row0 + m0 + mb * 16 + g;
        #pragma unroll
        for (int nb = 0; nb < 8; nb++) {
            int gc = col0 + n0 + nb * 8 + tig * 2;
            if (gc < Nact) {
                if (gr < M)
                    *(float2*)(C + (size_t)gr * ldc + gc) = make_float2(d[mb][nb][0], d[mb][nb][1]);
                if (gr + 8 < M)
                    *(float2*)(C + (size_t)(gr + 8) * ldc + gc) = make_float2(d[mb][nb][2], d[mb][nb][3]);
            }
        }
    }
}

// plain GEMM wrapper (vocab precompute)
__global__ __launch_bounds__(256, 2)
void k_mma_g(const __half* __restrict__ A, int M, int Kpad,
             const __half* __restrict__ B, int Nact, float* __restrict__ C, int ldc)
{
    extern __shared__ char smem[];
    gemm_core(blockIdx.x, blockIdx.y, smem, A, M, Kpad, B, Nact, C, ldc);
}

// merged per-level wrapper: segment 0 = psum @ U_iou (M x 450),
//                           segment 1 = h_children @ U_f (2M x 150)
__global__ __launch_bounds__(256, 2)
void k_mma_lvl(const __half* __restrict__ A1, int M1, float* __restrict__ C1,
               const __half* __restrict__ A2, int M2, float* __restrict__ C2,
               const __half* __restrict__ Bu, int nby1)
{
    extern __shared__ char smem[];
    int b = blockIdx.x;
    int total1 = nby1 << 2;
    if (b < total1) {
        gemm_core(b & 3, b >> 2, smem, A1, M1, KPU, Bu, HS3, C1, HS3);
    } else {
        b -= total1;
        gemm_core(b & 1, b >> 1, smem, A2, M2, KPU, Bu + (size_t)HS3 * KPU, HS, C2, HS);
    }
}

// ---------------- leaf level: gates + fused pair-sum + fused out ------------------
__global__ __launch_bounds__(320)
void k_leaf(const int* __restrict__ xid, const float* __restrict__ biou,
            const float* __restrict__ Wout, const float* __restrict__ bout,
            float* __restrict__ out)
{
    __shared__ float sh[300];
    const int t = threadIdx.x;
    const int b = blockIdx.x;
    if (t < 300) {
        int child = (t >= 150);
        int j = t - child * 150;
        int i = 2 * b + child;
        int n = (LEAVES - 1) + i;
        const float* ew = g_EW + (size_t)xid[n] * NPACK;
        float iv = ew[j] + biou[j];
        float ov = ew[HS + j] + biou[HS + j];
        float uv = ew[2 * HS + j] + biou[2 * HS + j];
        float cv = sig_f(iv) * tanh_f(uv);
        float hv = sig_f(ov) * tanh_f(cv);
        g_c[(size_t)n * HS + j] = cv;
        g_hf[(size_t)n * KPU + j] = __float2half_rn(hv);
        sh[t] = hv;
    }
    __syncthreads();
    if (t < 150) {
        float s = sh[t] + sh[150 + t];
        g_sf[(size_t)b * KPU + t] = __float2half_rn(s);
    }
    int w = t >> 5, lane = t & 31;
    if (w < 10) {
        int nd = w / 5, q = w - nd * 5;
        float a = 0.f;
        for (int j = lane; j < HS; j += 32)
            a = fmaf(sh[nd * HS + j], Wout[j * NC + q], a);
        #pragma unroll
        for (int off = 16; off; off >>= 1) a += __shfl_xor_sync(0xffffffffu, a, off);
        if (lane == 0) {
            int n = (LEAVES - 1) + 2 * b + nd;
            out[(size_t)n * NC + q] = a + bout[q];
        }
    }
}

// ---------------- internal-level combine + fused pair-sum + fused out -------------
__global__ __launch_bounds__(320)
void k_combine(int s, int cs, const int* __restrict__ xid,
               const float* __restrict__ biou, const float* __restrict__ bf,
               const float* __restrict__ Wout, const float* __restrict__ bout,
               float* __restrict__ out)
{
    __shared__ float sh[300];
    const int t = threadIdx.x;
    const int b = blockIdx.x;
    if (t < 300) {
        int child = (t >= 150);
        int j = t - child * 150;
        int k = 2 * b + child;
        int p = s + k;
        const float* ew  = g_EW + (size_t)xid[p] * NPACK;
        const float* hio = g_hiou + (size_t)k * HS3;
        float iv = ew[j]          + hio[j]          + biou[j];
        float ov = ew[HS + j]     + hio[HS + j]     + biou[HS + j];
        float uv = ew[2 * HS + j] + hio[2 * HS + j] + biou[2 * HS + j];
        float xf = ew[HS3 + j] + bf[j];
        float fl = sig_f(xf + g_hUf[(size_t)(2 * k) * HS + j]);
        float fr = sig_f(xf + g_hUf[(size_t)(2 * k + 1) * HS + j]);
        float cl = g_c[(size_t)(cs + 2 * k) * HS + j];
        float cr = g_c[(size_t)(cs + 2 * k + 1) * HS + j];
        float cv = sig_f(iv) * tanh_f(uv) + fl * cl + fr * cr;
        float hv = sig_f(ov) * tanh_f(cv);
        g_c[(size_t)p * HS + j] = cv;
        g_hf[(size_t)p * KPU + j] = __float2half_rn(hv);
        sh[t] = hv;
    }
    __syncthreads();
    if (t < 150) {
        float sum = sh[t] + sh[150 + t];
        g_sf[(size_t)b * KPU + t] = __float2half_rn(sum);
    }
    int w = t >> 5, lane = t & 31;
    if (w < 10) {
        int nd = w / 5, q = w - nd * 5;
        float a = 0.f;
        for (int j = lane; j < HS; j += 32)
            a = fmaf(sh[nd * HS + j], Wout[j * NC + q], a);
        #pragma unroll
        for (int off = 16; off; off >>= 1) a += __shfl_xor_sync(0xffffffffu, a, off);
        if (lane == 0) {
            int p = s + 2 * b + nd;
            out[(size_t)p * NC + q] = a + bout[q];
        }
    }
}

// ---------------- small levels: fused GEMV + gates + out (fp32 exact) -------------
__global__ __launch_bounds__(256)
void k_small(int s, int cs, const float* __restrict__ Uiou, const float* __restrict__ Uf,
             const int* __restrict__ xid, const float* __restrict__ biou,
             const float* __restrict__ bf,
             const float* __restrict__ Wout, const float* __restrict__ bout,
             float* __restrict__ out)
{
    __shared__ float hl_[HS], hr_[HS], hs_[HS], ho_[HS];
    __shared__ float io_[HS3], fl_[HS], fr_[HS];
    const int t = threadIdx.x;
    const int k = blockIdx.x;
    const int p = s + k;

    for (int j = t; j < HS; j += 256) {
        float hl = __half2float(g_hf[(size_t)(cs + 2 * k) * KPU + j]);
        float hr = __half2float(g_hf[(size_t)(cs + 2 * k + 1) * KPU + j]);
        hl_[j] = hl; hr_[j] = hr; hs_[j] = hl + hr;
    }
    __syncthreads();

    for (int j = t; j < HS3; j += 256) {
        float a = 0.0f;
        #pragma unroll 5
        for (int kk = 0; kk < HS; kk++) a = fmaf(hs_[kk], Uiou[kk * HS3 + j], a);
        io_[j] = a;
    }
    for (int j = t; j < HS; j += 256) {
        float al = 0.0f, ar = 0.0f;
        #pragma unroll 5
        for (int kk = 0; kk < HS; kk++) {
            float u = Uf[kk * HS + j];
            al = fmaf(hl_[kk], u, al);
            ar = fmaf(hr_[kk], u, ar);
        }
        fl_[j] = al; fr_[j] = ar;
    }
    __syncthreads();

    if (t < HS) {
        int j = t;
        const float* ew = g_EW + (size_t)xid[p] * NPACK;
        float iv = ew[j] + io_[j] + biou[j];
        float ov = ew[HS + j] + io_[HS + j] + biou[HS + j];
        float uv = ew[2 * HS + j] + io_[2 * HS + j] + biou[2 * HS + j];
        float xf = ew[HS3 + j] + bf[j];
        float fl = sig_f(xf + fl_[j]);
        float fr = sig_f(xf + fr_[j]);
        float cl = g_c[(size_t)(cs + 2 * k) * HS + j];
        float cr = g_c[(size_t)(cs + 2 * k + 1) * HS + j];
        float cv = sig_f(iv) * tanh_f(uv) + fl * cl + fr * cr;
        float hv = sig_f(ov) * tanh_f(cv);
        g_c[(size_t)p * HS + j] = cv;
        g_hf[(size_t)p * KPU + j] = __float2half_rn(hv);
        ho_[j] = hv;
    }
    __syncthreads();
    int w = t >> 5, lane = t & 31;
    if (w < NC) {
        float a = 0.f;
        for (int j = lane; j < HS; j += 32)
            a = fmaf(ho_[j], Wout[j * NC + w], a);
        #pragma unroll
        for (int off = 16; off; off >>= 1) a += __shfl_xor_sync(0xffffffffu, a, off);
        if (lane == 0) out[(size_t)p * NC + w] = a + bout[w];
    }
}

// ---------------- host orchestration ---------------------------------------------
extern "C" void kernel_launch(void* const* d_in, const int* in_sizes, int n_in,
                              void* d_out, int out_size)
{
    (void)in_sizes; (void)n_in; (void)out_size;
    const int*   xid  = (const int*)d_in[0];
    const float* emb  = (const float*)d_in[1];
    const float* Wiou = (const float*)d_in[2];
    const float* Uiou = (const float*)d_in[3];
    const float* biou = (const float*)d_in[4];
    const float* Wf   = (const float*)d_in[5];
    const float* Uf   = (const float*)d_in[6];
    const float* bf   = (const float*)d_in[7];
    const float* Wout = (const float*)d_in[8];
    const float* bout = (const float*)d_in[9];
    float* out = (float*)d_out;

    float *pEW, *pHiou, *pHUf;
    __half *pEf, *pBw, *pBu, *pHf, *pSf;
    cudaGetSymbolAddress((void**)&pEW,   g_EW);
    cudaGetSymbolAddress((void**)&pHiou, g_hiou);
    cudaGetSymbolAddress((void**)&pHUf,  g_hUf);
    cudaGetSymbolAddress((void**)&pEf,   g_Ef);
    cudaGetSymbolAddress((void**)&pBw,   g_Bw);
    cudaGetSymbolAddress((void**)&pBu,   g_Bu);
    cudaGetSymbolAddress((void**)&pHf,   g_hf);
    cudaGetSymbolAddress((void**)&pSf,   g_sf);

    cudaFuncSetAttribute(k_mma_g,   cudaFuncAttributeMaxDynamicSharedMemorySize, SMEMT);
    cudaFuncSetAttribute(k_mma_lvl, cudaFuncAttributeMaxDynamicSharedMemorySize, SMEMT);

    const dim3 thr(256);
    k_prep_w<<<(NBROW * KPW + NBROW * KPU + 255) / 256, thr>>>(Wiou, Wf, Uiou, Uf);
    k_prep_emb<<<(VPAD * KPW + 255) / 256, thr>>>(emb);
    {
        int zt = (NNODES + 128) * 10 + (LEAVES / 2) * 10;
        k_zeropads<<<(zt + 255) / 256, thr>>>();
    }

    // Vocab precompute: g_EW = emb @ [W_iou | W_f]
    k_mma_g<<<dim3(5, VPAD / 128), thr, SMEMT>>>(pEf, VOCAB, KPW, pBw, NPACK, pEW, NPACK);

    // Leaf level: gates + psum + out.
    k_leaf<<<LEAVES / 2, 320>>>(xid, biou, Wout, bout, out);

    // Levels 17..7: merged GEMM launch + combine.
    for (int lvl = DEPTH - 1; lvl >= LVL_SMALL; lvl--) {
        int M  = 1 << lvl;
        int s  = M - 1;
        int cs = 2 * M - 1;
        int nby1 = (M + 127) / 128;
        int nby2 = (2 * M + 127) / 128;
        int nblk = 4 * nby1 + 2 * nby2;
        k_mma_lvl<<<nblk, thr, SMEMT>>>(
            pSf, M, pHiou,
            pHf + (size_t)cs * KPU, 2 * M, pHUf,
            pBu, nby1);
        k_combine<<<M / 2, 320>>>(s, cs, xid, biou, bf, Wout, bout, out);
    }

    // Levels 6..0: fused GEMV path.
    for (int lvl = LVL_SMALL - 1; lvl >= 0; lvl--) {
        int M  = 1 << lvl;
        int s  = M - 1;
        int cs = 2 * M - 1;
        k_small<<<M, 256>>>(s, cs, Uiou, Uf, xid, biou, bf, Wout, bout, out);
    }
}

// round 8
// speedup vs baseline: 3.3113x; 1.0851x over previous
#include <cuda_runtime.h>
#include <cuda_fp16.h>
#include <cstdint>
#include <cstddef>

#define VOCAB   50000
#define VPAD    50048        // 391 * 128
#define XS      300
#define HS      150
#define HS3     450
#define NPACK   600          // [iou(450) | f(150)]
#define NBROW   768
#define NC      5
#define DEPTH   18
#define NNODES  524287
#define LEAVES  262144
#define KPW     320
#define KPU     160
#define LVL_SMALL 7

// ---------------- static device scratch ------------------------------------------
__device__ __half g_EW[(size_t)VOCAB * NPACK];            // emb @ [W_iou|W_f], fp16
__device__ __half g_hiou[(size_t)(LEAVES / 2) * HS3];     // psum @ U_iou, fp16
__device__ __half g_hUf[(size_t)LEAVES * HS];             // h @ U_f, fp16
__device__ float  g_c[(size_t)NNODES * HS];
__device__ __half g_hf[(size_t)(NNODES + 128) * KPU];     // h, fp16
__device__ __half g_sf[(size_t)(LEAVES / 2) * KPU];       // pair-sum h, fp16
__device__ __half g_Ef[(size_t)VPAD * KPW];               // emb, fp16
__device__ __half g_Bw[(size_t)NBROW * KPW];              // [W_iou|W_f]^T fp16
__device__ __half g_Bu[(size_t)NBROW * KPU];              // [U_iou|U_f]^T fp16

// ---------------- helpers ---------------------------------------------------------
__device__ __forceinline__ uint32_t smem_u32(const void* p) {
    uint32_t a;
    asm("{ .reg .u64 t; cvta.to.shared.u64 t, %1; cvt.u32.u64 %0, t; }" : "=r"(a) : "l"(p));
    return a;
}
#define CP16(dst, src) \
    asm volatile("cp.async.cg.shared.global [%0], [%1], 16;" :: "r"(dst), "l"(src))
#define CP_COMMIT() asm volatile("cp.async.commit_group;" ::: "memory")
#define CP_WAITG2() asm volatile("cp.async.wait_group 2;" ::: "memory")
#define LDSM4(r0, r1, r2, r3, addr)                                               \
    asm volatile("ldmatrix.sync.aligned.m8n8.x4.shared.b16 {%0,%1,%2,%3}, [%4];"  \
                 : "=r"(r0), "=r"(r1), "=r"(r2), "=r"(r3) : "r"(addr))
#define MMA_F16(d, a0, a1, a2, a3, b0, b1)                                       \
    asm volatile("mma.sync.aligned.m16n8k16.row.col.f32.f16.f16.f32 "            \
                 "{%0,%1,%2,%3},{%4,%5,%6,%7},{%8,%9},{%0,%1,%2,%3};"            \
                 : "+f"(d[0]), "+f"(d[1]), "+f"(d[2]), "+f"(d[3])                \
                 : "r"(a0), "r"(a1), "r"(a2), "r"(a3), "r"(b0), "r"(b1))

// ---------------- FMA-only activations -------------------------------------------
__device__ __forceinline__ float sig_f(float x) {
    float ax = fabsf(x);
    if (ax > 1.0f) return 1.0f / (1.0f + __expf(-x));
    float x2 = x * x;
    float p = fmaf(x2, 2.1357958e-5f, -2.1081349e-4f);
    p = fmaf(x2, p, 2.0833333e-3f);
    p = fmaf(x2, p, -2.0833333e-2f);
    p = fmaf(x2, p, 0.25f);
    return fmaf(x, p, 0.5f);
}
__device__ __forceinline__ float tanh_f(float x) {
    float ax = fabsf(x);
    if (ax > 0.55f) {
        float t = __expf(-2.0f * ax);
        float r = __fdividef(1.0f - t, 1.0f + t);
        return x < 0.0f ? -r : r;
    }
    float x2 = x * x;
    float p = fmaf(x2, 2.1869488e-2f, -5.3968254e-2f);
    p = fmaf(x2, p, 1.3333333e-1f);
    p = fmaf(x2, p, -3.3333333e-1f);
    p = fmaf(x2, p, 1.0f);
    return x * p;
}

// ---------------- prep kernels ----------------------------------------------------
__global__ void k_prep_w(const float* __restrict__ Wiou, const float* __restrict__ Wf,
                         const float* __restrict__ Uiou, const float* __restrict__ Uf)
{
    int idx = blockIdx.x * blockDim.x + threadIdx.x;
    const int NW = NBROW * KPW;
    const int NU = NBROW * KPU;
    if (idx < NW) {
        int n = idx / KPW, k = idx - n * KPW;
        float v = 0.0f;
        if (k < XS && n < NPACK) v = (n < HS3) ? Wiou[k * HS3 + n] : Wf[k * HS + (n - HS3)];
        g_Bw[idx] = __float2half_rn(v);
    } else if (idx < NW + NU) {
        int j = idx - NW;
        int n = j / KPU, k = j - n * KPU;
        float v = 0.0f;
        if (k < HS && n < NPACK) v = (n < HS3) ? Uiou[k * HS3 + n] : Uf[k * HS + (n - HS3)];
        g_Bu[j] = __float2half_rn(v);
    }
}

__global__ void k_prep_emb(const float* __restrict__ emb)
{
    int idx = blockIdx.x * blockDim.x + threadIdx.x;
    if (idx >= VPAD * KPW) return;
    int r = idx / KPW, k = idx - r * KPW;
    float v = (r < VOCAB && k < XS) ? emb[(size_t)r * XS + k] : 0.0f;
    g_Ef[idx] = __float2half_rn(v);
}

__global__ void k_zeropads()
{
    int idx = blockIdx.x * blockDim.x + threadIdx.x;
    const int T1 = (NNODES + 128) * 10;
    const int T2 = (LEAVES / 2) * 10;
    if (idx < T1) {
        int r = idx / 10, k = HS + idx % 10;
        g_hf[(size_t)r * KPU + k] = __float2half_rn(0.0f);
    } else if (idx < T1 + T2) {
        int j = idx - T1;
        int r = j / 10, k = HS + j % 10;
        g_sf[(size_t)r * KPU + k] = __float2half_rn(0.0f);
    }
}

// ---------------- cp.async(4-stage) + ldmatrix fp16 mma.sync GEMM core ------------
#define SROW   20                     // u32 per smem row (64B data + 16B pad)
#define PLANEB 10240                  // 128 rows * 80B
#define STAGEB 20480                  // 2 planes (A, B)
#define NSTAGE 4
#define SMEMT  (NSTAGE * STAGEB)      // 81920

// OUTH=1: write fp16 C; OUTH=0: write fp32 C.
template <int OUTH>
__device__ __forceinline__ void gemm_core(
    int bx, int by, char* smem,
    const __half* __restrict__ A, int M, int Kpad,
    const __half* __restrict__ B, int Nact, void* __restrict__ C, int ldc)
{
    const uint32_t sb = smem_u32(smem);
    const int tid  = threadIdx.x;
    const int lane = tid & 31;
    const int wid  = tid >> 5;
    const int row0 = by << 7;
    const int col0 = bx << 7;
    const int m0 = (wid & 3) << 5;
    const int n0 = (wid >> 2) << 6;
    const int g   = lane >> 2;
    const int tig = lane & 3;

    const int lr   = lane & 7;
    const uint32_t aOff = (uint32_t)(m0 + lr + (((lane >> 3) & 1) << 3)) * 80
                        + (uint32_t)((lane >> 4) << 4);
    const uint32_t bOff = (uint32_t)(n0 + lr + ((lane >> 4) << 3)) * 80
                        + (uint32_t)(((lane >> 3) & 1) << 4);

    const char* pA = (const char*)(A + (size_t)row0 * Kpad);
    const char* pB = (const char*)(B + (size_t)col0 * Kpad);

    const int r_ld = tid >> 1;
    const int sg2  = (tid & 1) << 1;

    float d[2][8][4];
    #pragma unroll
    for (int mb = 0; mb < 2; mb++)
        #pragma unroll
        for (int nb = 0; nb < 8; nb++)
            #pragma unroll
            for (int q = 0; q < 4; q++) d[mb][nb][q] = 0.0f;

    auto load_chunk = [&](int kb, int st) {
        uint32_t dbase = sb + st * STAGEB + r_ld * 80 + sg2 * 16;
        size_t   soff  = ((size_t)r_ld * Kpad + kb + sg2 * 8) * 2;
        CP16(dbase,               pA + soff);
        CP16(dbase + 16,          pA + soff + 16);
        CP16(dbase + PLANEB,      pB + soff);
        CP16(dbase + PLANEB + 16, pB + soff + 16);
    };

    const int chunks = Kpad >> 5;          // >= 5 in all uses
    #pragma unroll
    for (int s = 0; s < NSTAGE - 1; s++) {
        load_chunk(s << 5, s);
        CP_COMMIT();
    }

    for (int c = 0; c < chunks; c++) {
        CP_WAITG2();
        __syncthreads();

        const uint32_t sbase = sb + (c & (NSTAGE - 1)) * STAGEB;

        #pragma unroll
        for (int ks = 0; ks < 2; ks++) {
            uint32_t ah[2][4];
            #pragma unroll
            for (int mb = 0; mb < 2; mb++) {
                uint32_t aoff = sbase + aOff + mb * (16 * 80) + ks * 32;
                LDSM4(ah[mb][0], ah[mb][1], ah[mb][2], ah[mb][3], aoff);
            }
            #pragma unroll
            for (int pr = 0; pr < 4; pr++) {
                uint32_t boff = sbase + PLANEB + bOff + pr * (16 * 80) + ks * 32;
                uint32_t bh[4];
                LDSM4(bh[0], bh[1], bh[2], bh[3], boff);
                #pragma unroll
                for (int mb = 0; mb < 2; mb++) {
                    MMA_F16(d[mb][2 * pr],     ah[mb][0], ah[mb][1], ah[mb][2], ah[mb][3], bh[0], bh[1]);
                    MMA_F16(d[mb][2 * pr + 1], ah[mb][0], ah[mb][1], ah[mb][2], ah[mb][3], bh[2], bh[3]);
                }
            }
        }
        __syncthreads();
        if (c + NSTAGE - 1 < chunks)
            load_chunk((c + NSTAGE - 1) << 5, (c + NSTAGE - 1) & (NSTAGE - 1));
        CP_COMMIT();
    }

    #pragma unroll
    for (int mb = 0; mb < 2; mb++) {
        int gr = row0 + m0 + mb * 16 + g;
        #pragma unroll
        for (int nb = 0; nb < 8; nb++) {
            int gc = col0 + n0 + nb * 8 + tig * 2;
            if (gc < Nact) {
                if (OUTH) {
                    __half* Ch = (__half*)C;
                    if (gr < M)
                        *(__half2*)(Ch + (size_t)gr * ldc + gc) =
                            __floats2half2_rn(d[mb][nb][0], d[mb][nb][1]);
                    if (gr + 8 < M)
                        *(__half2*)(Ch + (size_t)(gr + 8) * ldc + gc) =
                            __floats2half2_rn(d[mb][nb][2], d[mb][nb][3]);
                } else {
                    float* Cf = (float*)C;
                    if (gr < M)
                        *(float2*)(Cf + (size_t)gr * ldc + gc) = make_float2(d[mb][nb][0], d[mb][nb][1]);
                    if (gr + 8 < M)
                        *(float2*)(Cf + (size_t)(gr + 8) * ldc + gc) = make_float2(d[mb][nb][2], d[mb][nb][3]);
                }
            }
        }
    }
}

// vocab precompute wrapper (fp16 out)
__global__ __launch_bounds__(256, 2)
void k_mma_g(const __half* __restrict__ A, int M, int Kpad,
             const __half* __restrict__ B, int Nact, __half* __restrict__ C, int ldc)
{
    extern __shared__ char smem[];
    gemm_core<1>(blockIdx.x, blockIdx.y, smem, A, M, Kpad, B, Nact, C, ldc);
}

// merged per-level wrapper (fp16 out): seg0 = psum @ U_iou; seg1 = h @ U_f
__global__ __launch_bounds__(256, 2)
void k_mma_lvl(const __half* __restrict__ A1, int M1, __half* __restrict__ C1,
               const __half* __restrict__ A2, int M2, __half* __restrict__ C2,
               const __half* __restrict__ Bu, int nby1)
{
    extern __shared__ char smem[];
    int b = blockIdx.x;
    int total1 = nby1 << 2;
    if (b < total1) {
        gemm_core<1>(b & 3, b >> 2, smem, A1, M1, KPU, Bu, HS3, C1, HS3);
    } else {
        b -= total1;
        gemm_core<1>(b & 1, b >> 1, smem, A2, M2, KPU, Bu + (size_t)HS3 * KPU, HS, C2, HS);
    }
}

// ---------------- leaf level: gates + fused pair-sum + fused out ------------------
__global__ __launch_bounds__(320)
void k_leaf(const int* __restrict__ xid, const float* __restrict__ biou,
            const float* __restrict__ Wout, const float* __restrict__ bout,
            float* __restrict__ out)
{
    __shared__ float sh[300];
    const int t = threadIdx.x;
    const int b = blockIdx.x;
    if (t < 300) {
        int child = (t >= 150);
        int j = t - child * 150;
        int i = 2 * b + child;
        int n = (LEAVES - 1) + i;
        const __half* ew = g_EW + (size_t)xid[n] * NPACK;
        float iv = __half2float(ew[j]) + biou[j];
        float ov = __half2float(ew[HS + j]) + biou[HS + j];
        float uv = __half2float(ew[2 * HS + j]) + biou[2 * HS + j];
        float cv = sig_f(iv) * tanh_f(uv);
        float hv = sig_f(ov) * tanh_f(cv);
        g_c[(size_t)n * HS + j] = cv;
        g_hf[(size_t)n * KPU + j] = __float2half_rn(hv);
        sh[t] = hv;
    }
    __syncthreads();
    if (t < 150) {
        float s = sh[t] + sh[150 + t];
        g_sf[(size_t)b * KPU + t] = __float2half_rn(s);
    }
    int w = t >> 5, lane = t & 31;
    if (w < 10) {
        int nd = w / 5, q = w - nd * 5;
        float a = 0.f;
        for (int j = lane; j < HS; j += 32)
            a = fmaf(sh[nd * HS + j], Wout[j * NC + q], a);
        #pragma unroll
        for (int off = 16; off; off >>= 1) a += __shfl_xor_sync(0xffffffffu, a, off);
        if (lane == 0) {
            int n = (LEAVES - 1) + 2 * b + nd;
            out[(size_t)n * NC + q] = a + bout[q];
        }
    }
}

// ---------------- internal-level combine + fused pair-sum + fused out -------------
__global__ __launch_bounds__(320)
void k_combine(int s, int cs, const int* __restrict__ xid,
               const float* __restrict__ biou, const float* __restrict__ bf,
               const float* __restrict__ Wout, const float* __restrict__ bout,
               float* __restrict__ out)
{
    __shared__ float sh[300];
    const int t = threadIdx.x;
    const int b = blockIdx.x;
    if (t < 300) {
        int child = (t >= 150);
        int j = t - child * 150;
        int k = 2 * b + child;
        int p = s + k;
        const __half* ew  = g_EW + (size_t)xid[p] * NPACK;
        const __half* hio = g_hiou + (size_t)k * HS3;
        float iv = __half2float(ew[j])          + __half2float(hio[j])          + biou[j];
        float ov = __half2float(ew[HS + j])     + __half2float(hio[HS + j])     + biou[HS + j];
        float uv = __half2float(ew[2 * HS + j]) + __half2float(hio[2 * HS + j]) + biou[2 * HS + j];
        float xf = __half2float(ew[HS3 + j]) + bf[j];
        float fl = sig_f(xf + __half2float(g_hUf[(size_t)(2 * k) * HS + j]));
        float fr = sig_f(xf + __half2float(g_hUf[(size_t)(2 * k + 1) * HS + j]));
        float cl = g_c[(size_t)(cs + 2 * k) * HS + j];
        float cr = g_c[(size_t)(cs + 2 * k + 1) * HS + j];
        float cv = sig_f(iv) * tanh_f(uv) + fl * cl + fr * cr;
        float hv = sig_f(ov) * tanh_f(cv);
        g_c[(size_t)p * HS + j] = cv;
        g_hf[(size_t)p * KPU + j] = __float2half_rn(hv);
        sh[t] = hv;
    }
    __syncthreads();
    if (t < 150) {
        float sum = sh[t] + sh[150 + t];
        g_sf[(size_t)b * KPU + t] = __float2half_rn(sum);
    }
    int w = t >> 5, lane = t & 31;
    if (w < 10) {
        int nd = w / 5, q = w - nd * 5;
        float a = 0.f;
        for (int j = lane; j < HS; j += 32)
            a = fmaf(sh[nd * HS + j], Wout[j * NC + q], a);
        #pragma unroll
        for (int off = 16; off; off >>= 1) a += __shfl_xor_sync(0xffffffffu, a, off);
        if (lane == 0) {
            int p = s + 2 * b + nd;
            out[(size_t)p * NC + q] = a + bout[q];
        }
    }
}

// ---------------- small levels: fused GEMV + gates + out (fp32) -------------------
__global__ __launch_bounds__(256)
void k_small(int s, int cs, const float* __restrict__ Uiou, const float* __restrict__ Uf,
             const int* __restrict__ xid, const float* __restrict__ biou,
             const float* __restrict__ bf,
             const float* __restrict__ Wout, const float* __restrict__ bout,
             float* __restrict__ out)
{
    __shared__ float hl_[HS], hr_[HS], hs_[HS], ho_[HS];
    __shared__ float io_[HS3], fl_[HS], fr_[HS];
    const int t = threadIdx.x;
    const int k = blockIdx.x;
    const int p = s + k;

    for (int j = t; j < HS; j += 256) {
        float hl = __half2float(g_hf[(size_t)(cs + 2 * k) * KPU + j]);
        float hr = __half2float(g_hf[(size_t)(cs + 2 * k + 1) * KPU + j]);
        hl_[j] = hl; hr_[j] = hr; hs_[j] = hl + hr;
    }
    __syncthreads();

    for (int j = t; j < HS3; j += 256) {
        float a = 0.0f;
        #pragma unroll 5
        for (int kk = 0; kk < HS; kk++) a = fmaf(hs_[kk], Uiou[kk * HS3 + j], a);
        io_[j] = a;
    }
    for (int j = t; j < HS; j += 256) {
        float al = 0.0f, ar = 0.0f;
        #pragma unroll 5
        for (int kk = 0; kk < HS; kk++) {
            float u = Uf[kk * HS + j];
            al = fmaf(hl_[kk], u, al);
            ar = fmaf(hr_[kk], u, ar);
        }
        fl_[j] = al; fr_[j] = ar;
    }
    __syncthreads();

    if (t < HS) {
        int j = t;
        const __half* ew = g_EW + (size_t)xid[p] * NPACK;
        float iv = __half2float(ew[j]) + io_[j] + biou[j];
        float ov = __half2float(ew[HS + j]) + io_[HS + j] + biou[HS + j];
        float uv = __half2float(ew[2 * HS + j]) + io_[2 * HS + j] + biou[2 * HS + j];
        float xf = __half2float(ew[HS3 + j]) + bf[j];
        float fl = sig_f(xf + fl_[j]);
        float fr = sig_f(xf + fr_[j]);
        float cl = g_c[(size_t)(cs + 2 * k) * HS + j];
        float cr = g_c[(size_t)(cs + 2 * k + 1) * HS + j];
        float cv = sig_f(iv) * tanh_f(uv) + fl * cl + fr * cr;
        float hv = sig_f(ov) * tanh_f(cv);
        g_c[(size_t)p * HS + j] = cv;
        g_hf[(size_t)p * KPU + j] = __float2half_rn(hv);
        ho_[j] = hv;
    }
    __syncthreads();
    int w = t >> 5, lane = t & 31;
    if (w < NC) {
        float a = 0.f;
        for (int j = lane; j < HS; j += 32)
            a = fmaf(ho_[j], Wout[j * NC + w], a);
        #pragma unroll
        for (int off = 16; off; off >>= 1) a += __shfl_xor_sync(0xffffffffu, a, off);
        if (lane == 0) out[(size_t)p * NC + w] = a + bout[w];
    }
}

// ---------------- host orchestration ---------------------------------------------
extern "C" void kernel_launch(void* const* d_in, const int* in_sizes, int n_in,
                              void* d_out, int out_size)
{
    (void)in_sizes; (void)n_in; (void)out_size;
    const int*   xid  = (const int*)d_in[0];
    const float* emb  = (const float*)d_in[1];
    const float* Wiou = (const float*)d_in[2];
    const float* Uiou = (const float*)d_in[3];
    const float* biou = (const float*)d_in[4];
    const float* Wf   = (const float*)d_in[5];
    const float* Uf   = (const float*)d_in[6];
    const float* bf   = (const float*)d_in[7];
    const float* Wout = (const float*)d_in[8];
    const float* bout = (const float*)d_in[9];
    float* out = (float*)d_out;

    __half *pEW, *pHiou, *pHUf, *pEf, *pBw, *pBu, *pHf, *pSf;
    cudaGetSymbolAddress((void**)&pEW,   g_EW);
    cudaGetSymbolAddress((void**)&pHiou, g_hiou);
    cudaGetSymbolAddress((void**)&pHUf,  g_hUf);
    cudaGetSymbolAddress((void**)&pEf,   g_Ef);
    cudaGetSymbolAddress((void**)&pBw,   g_Bw);
    cudaGetSymbolAddress((void**)&pBu,   g_Bu);
    cudaGetSymbolAddress((void**)&pHf,   g_hf);
    cudaGetSymbolAddress((void**)&pSf,   g_sf);

    cudaFuncSetAttribute(k_mma_g,   cudaFuncAttributeMaxDynamicSharedMemorySize, SMEMT);
    cudaFuncSetAttribute(k_mma_lvl, cudaFuncAttributeMaxDynamicSharedMemorySize, SMEMT);

    const dim3 thr(256);
    k_prep_w<<<(NBROW * KPW + NBROW * KPU + 255) / 256, thr>>>(Wiou, Wf, Uiou, Uf);
    k_prep_emb<<<(VPAD * KPW + 255) / 256, thr>>>(emb);
    {
        int zt = (NNODES + 128) * 10 + (LEAVES / 2) * 10;
        k_zeropads<<<(zt + 255) / 256, thr>>>();
    }

    // Vocab precompute: g_EW = emb @ [W_iou | W_f]  (fp16 out)
    k_mma_g<<<dim3(5, VPAD / 128), thr, SMEMT>>>(pEf, VOCAB, KPW, pBw, NPACK, pEW, NPACK);

    // Leaf level: gates + psum + out.
    k_leaf<<<LEAVES / 2, 320>>>(xid, biou, Wout, bout, out);

    // Levels 17..7: merged GEMM launch + combine.
    for (int lvl = DEPTH - 1; lvl >= LVL_SMALL; lvl--) {
        int M  = 1 << lvl;
        int s  = M - 1;
        int cs = 2 * M - 1;
        int nby1 = (M + 127) / 128;
        int nby2 = (2 * M + 127) / 128;
        int nblk = 4 * nby1 + 2 * nby2;
        k_mma_lvl<<<nblk, thr, SMEMT>>>(
            pSf, M, pHiou,
            pHf + (size_t)cs * KPU, 2 * M, pHUf,
            pBu, nby1);
        k_combine<<<M / 2, 320>>>(s, cs, xid, biou, bf, Wout, bout, out);
    }

    // Levels 6..0: fused GEMV path.
    for (int lvl = LVL_SMALL - 1; lvl >= 0; lvl--) {
        int M  = 1 << lvl;
        int s  = M - 1;
        int cs = 2 * M - 1;
        k_small<<<M, 256>>>(s, cs, Uiou, Uf, xid, biou, bf, Wout, bout, out);
    }
}